// round 8
// baseline (speedup 1.0000x reference)
#include <cuda_runtime.h>
#include <math.h>
#include <stdint.h>

#define B_    8
#define N_    512
#define T_    64
#define NIN_  64
#define NEMB_ 128
#define NH_   128
#define ROWS_ (B_ * N_)
#define ZSTR  392   // padded z row stride (floats)

typedef unsigned long long u64;

// ---------------- device scratch ----------------
__device__ float g_An[B_ * N_ * N_];
__device__ float g_dinv[ROWS_];
__device__ float g_es[ROWS_ * NEMB_];
__device__ float g_h[2][ROWS_ * NH_];
__device__ float g_c[ROWS_ * NH_];
__device__ float g_Wz[384 * 512];     // fused gate weights [k=384][col=4*128 (i|f|g|o)]
__device__ float g_bz[512];           // fused gate bias

// ---------------- packed f32x2 helpers ----------------
__device__ __forceinline__ u64 pk2(float x, float y) {
  u64 r; asm("mov.b64 %0, {%1, %2};" : "=l"(r) : "f"(x), "f"(y)); return r;
}
__device__ __forceinline__ u64 bc2(float x) { return pk2(x, x); }
__device__ __forceinline__ void up2(u64 v, float& x, float& y) {
  asm("mov.b64 {%0, %1}, %2;" : "=f"(x), "=f"(y) : "l"(v));
}
__device__ __forceinline__ void fma2(u64& d, u64 a, u64 b) {
  asm("fma.rn.f32x2 %0, %1, %2, %0;" : "+l"(d) : "l"(a), "l"(b));
}
// fast sigmoid (ex2/rcp approx: ~1e-7 err). tanh stays accurate (tanhf).
__device__ __forceinline__ float fsgm(float x) {
  float e; asm("ex2.approx.f32 %0, %1;" : "=f"(e) : "f"(-1.4426950408889634f * x));
  float r; asm("rcp.approx.f32 %0, %1;" : "=f"(r) : "f"(1.0f + e));
  return r;
}
// cp.async
__device__ __forceinline__ uint32_t s2u(const void* p) {
  return (uint32_t)__cvta_generic_to_shared(p);
}
__device__ __forceinline__ void cp16(uint32_t d, const void* s) {
  asm volatile("cp.async.cg.shared.global [%0], [%1], 16;\n" :: "r"(d), "l"(s));
}
__device__ __forceinline__ void cpcommit() { asm volatile("cp.async.commit_group;\n"); }
template <int N> __device__ __forceinline__ void cpwait() {
  asm volatile("cp.async.wait_group %0;\n" :: "n"(N));
}

// ---------------- preamble kernels ----------------
__global__ void k_dinv(const float* __restrict__ A) {
  int row = blockIdx.x;
  const float* ap = A + (size_t)row * N_;
  float s = 0.0f;
  for (int m = threadIdx.x; m < N_; m += blockDim.x) s += ap[m];
  __shared__ float red[128];
  red[threadIdx.x] = s;
  __syncthreads();
  for (int off = 64; off; off >>= 1) {
    if (threadIdx.x < off) red[threadIdx.x] += red[threadIdx.x + off];
    __syncthreads();
  }
  if (threadIdx.x == 0) {
    float d = red[0];
    g_dinv[row] = (d > 0.0f) ? (1.0f / sqrtf(d)) : 0.0f;
  }
}

__global__ void k_an(const float* __restrict__ A) {
  size_t total = (size_t)B_ * N_ * N_;
  for (size_t i = blockIdx.x * (size_t)blockDim.x + threadIdx.x; i < total;
       i += (size_t)gridDim.x * blockDim.x) {
    int m = (int)(i & 511);
    size_t r = i >> 9;
    int n = (int)(r & 511);
    int b = (int)(r >> 9);
    g_An[i] = A[i] * g_dinv[b * N_ + n] * g_dinv[b * N_ + m];
  }
}

__global__ void k_init(const float* __restrict__ X, const float* __restrict__ Wse,
                       const float* __restrict__ bse, float* __restrict__ out) {
  int tid = blockIdx.x * blockDim.x + threadIdx.x;
  int row = tid >> 7;
  int c = tid & 127;
  const float* x0 = X + (size_t)row * (T_ * NIN_);
  float acc = bse[c];
  #pragma unroll 8
  for (int k = 0; k < NIN_; k++) acc += x0[k] * Wse[k * NEMB_ + c];
  g_es[(size_t)row * NEMB_ + c] = acc;
  g_h[0][tid] = 0.0f;
  g_c[tid] = 0.0f;
  if (c < NIN_) out[(size_t)row * (T_ * NIN_) + c] = x0[c];
}

struct StepP {
  const float *Wpe, *bpe, *Wii, *bii, *Whi, *bhi, *Wif, *bif, *Whf, *bhf,
              *Wig, *big, *Whg, *bhg, *Wio, *bio, *Who, *bho, *Wout, *bout;
  float* out;
};

__global__ void k_fuse(StepP p) {
  int i = blockIdx.x * blockDim.x + threadIdx.x;
  if (i < 384 * 512) {
    int c = i & 511, r = i >> 9, q = c >> 7, cc = c & 127;
    const float* W;
    if (r < 256)
      W = (q == 0 ? p.Wii : q == 1 ? p.Wif : q == 2 ? p.Wig : p.Wio) + r * 128;
    else
      W = (q == 0 ? p.Whi : q == 1 ? p.Whf : q == 2 ? p.Whg : p.Who) + (r - 256) * 128;
    g_Wz[i] = W[cc];
  }
  if (i < 512) {
    int q = i >> 7, cc = i & 127;
    const float* bx = q == 0 ? p.bii : q == 1 ? p.bif : q == 2 ? p.big : p.bio;
    const float* bh = q == 0 ? p.bhi : q == 1 ? p.bhf : q == 2 ? p.bhg : p.bho;
    g_bz[i] = bx[cc] + bh[cc];
  }
}

// ---------------- step kernel (512 threads) ----------------
// smem float offsets
#define SM_ZS   0                  // 32 x ZSTR = 12544
#define SM_HS   12544              // 32 x 128  = 4096
#define SM_BUFA 16640              // hs[2][64*128]=16384 + As[2][32*64]=4096 ; later Wout[128*64]=8192
#define SM_BUFB 37120              // WpeS[128*128]=16384 ; later Wz[2][16*512]=16384
#define SM_TOTF 53504              // floats (214,016 B)

__global__ void __launch_bounds__(512, 1) k_step(StepP p, int t) {
  extern __shared__ float sm[];
  float* zs    = sm + SM_ZS;    // [32][ZSTR]: 0:128 es | 128:256 eh | 256:384 h_prev
  float* Hs    = sm + SM_HS;    // [32][128] H, later h_t
  float* hsbuf = sm + SM_BUFA;              // [2][64*128]
  float* Asbuf = sm + SM_BUFA + 16384;      // [2][32*64]
  float* WoutS = sm + SM_BUFA;              // [128][64] (aliases hsbuf after GEMM1)
  float* WpeS  = sm + SM_BUFB;              // [128][128]
  float* WzS   = sm + SM_BUFB;              // [2][16*512] (aliases WpeS after eh)

  const float* hprev = g_h[(t - 1) & 1];
  float* hnext = g_h[t & 1];

  const int b = blockIdx.y;
  const int r0 = blockIdx.x * 32;
  const int tid = threadIdx.x;

  const float* esb = g_es + (size_t)(b * N_ + r0) * NEMB_;
  const float* hpb = hprev + (size_t)b * N_ * NH_;
  const float* hpr = hpb + (size_t)r0 * NH_;
  const float* Anb = g_An + (size_t)(b * N_ + r0) * N_;

  // --- group 1: zs (es + h_prev slice): 1024 float4 pairs, 512 thr x 2 ---
  #pragma unroll
  for (int j = 0; j < 2; j++) {
    int idx = tid + j * 512;
    int r = idx >> 5, c4 = (idx & 31) * 4;
    cp16(s2u(zs + r * ZSTR + c4), esb + r * NEMB_ + c4);
    cp16(s2u(zs + r * ZSTR + 256 + c4), hpr + r * NH_ + c4);
  }
  cpcommit();
  // --- group 2: Wpe stage (4096 float4) ---
  #pragma unroll
  for (int j = 0; j < 8; j++) {
    int idx = tid + j * 512;
    int r = idx >> 5, c4 = (idx & 31) * 4;
    cp16(s2u(WpeS + r * 128 + c4), p.Wpe + r * 128 + c4);
  }
  cpcommit();

  // --- GEMM1: H[32x128] = An_tile @ h_prev, K=512, chunks of 64 ---
  // thread -> 1 row x 8 cols
  const int rA = tid >> 4;            // 0..31
  const int cblk = tid & 15;          // col block: 8 floats
  const int c0 = cblk * 8;

  // prefetch chunk 0
  {
    #pragma unroll
    for (int j = 0; j < 4; j++) {
      int idx = tid + j * 512;
      int r = idx >> 5, c4 = (idx & 31) * 4;
      cp16(s2u(hsbuf + r * 128 + c4), hpb + (size_t)r * NH_ + c4);
    }
    {
      int r = tid >> 4, k4 = (tid & 15) * 4;
      cp16(s2u(Asbuf + r * 64 + k4), Anb + (size_t)r * N_ + k4);
    }
  }
  cpcommit();

  u64 aH[4];
  aH[0] = aH[1] = aH[2] = aH[3] = 0ull;

  #pragma unroll 1
  for (int ch = 0; ch < 8; ch++) {
    if (ch < 7) {
      int nb = (ch + 1) & 1;
      int k0 = (ch + 1) * 64;
      #pragma unroll
      for (int j = 0; j < 4; j++) {
        int idx = tid + j * 512;
        int r = idx >> 5, c4 = (idx & 31) * 4;
        cp16(s2u(hsbuf + nb * 8192 + r * 128 + c4), hpb + (size_t)(k0 + r) * NH_ + c4);
      }
      {
        int r = tid >> 4, k4 = (tid & 15) * 4;
        cp16(s2u(Asbuf + nb * 2048 + r * 64 + k4), Anb + (size_t)r * N_ + k0 + k4);
      }
      cpcommit();
      cpwait<1>();
    } else {
      cpwait<0>();
    }
    __syncthreads();
    const float* hc = hsbuf + (ch & 1) * 8192;
    const float* Ac = Asbuf + (ch & 1) * 2048;
    #pragma unroll 4
    for (int kk = 0; kk < 64; kk += 4) {
      float4 av = *(const float4*)(Ac + rA * 64 + kk);
      float ac[4] = {av.x, av.y, av.z, av.w};
      #pragma unroll
      for (int s = 0; s < 4; s++) {
        u64 A0 = bc2(ac[s]);
        const float* hrow = hc + (kk + s) * 128 + c0;
        ulonglong2 w0 = *(const ulonglong2*)(hrow);
        ulonglong2 w1 = *(const ulonglong2*)(hrow + 4);
        fma2(aH[0], A0, w0.x); fma2(aH[1], A0, w0.y);
        fma2(aH[2], A0, w1.x); fma2(aH[3], A0, w1.y);
      }
    }
    __syncthreads();
  }

  // store H to Hs
  {
    float4 v;
    up2(aH[0], v.x, v.y); up2(aH[1], v.z, v.w);
    *(float4*)(Hs + rA * 128 + c0) = v;
    up2(aH[2], v.x, v.y); up2(aH[3], v.z, v.w);
    *(float4*)(Hs + rA * 128 + c0 + 4) = v;
  }
  // prefetch Wout into bufA (GEMM1 done with it): 2048 float4
  #pragma unroll
  for (int j = 0; j < 4; j++) {
    int idx = tid + j * 512;
    int r = idx >> 4, c4 = (idx & 15) * 4;
    cp16(s2u(WoutS + r * 64 + c4), p.Wout + r * 64 + c4);
  }
  cpcommit();
  __syncthreads();

  // --- eh = H @ Wpe + bpe -> zs[:,128:256] ; thread: 1 row x 8 cols ---
  {
    u64 aE[4];
    ulonglong2 b0 = *(const ulonglong2*)(p.bpe + c0);
    ulonglong2 b1 = *(const ulonglong2*)(p.bpe + c0 + 4);
    aE[0] = b0.x; aE[1] = b0.y; aE[2] = b1.x; aE[3] = b1.y;
    #pragma unroll 4
    for (int k = 0; k < 128; k += 4) {
      float4 av = *(const float4*)(Hs + rA * 128 + k);
      float ac[4] = {av.x, av.y, av.z, av.w};
      #pragma unroll
      for (int s = 0; s < 4; s++) {
        u64 A0 = bc2(ac[s]);
        const float* wrow = WpeS + (k + s) * 128 + c0;
        ulonglong2 w0 = *(const ulonglong2*)(wrow);
        ulonglong2 w1 = *(const ulonglong2*)(wrow + 4);
        fma2(aE[0], A0, w0.x); fma2(aE[1], A0, w0.y);
        fma2(aE[2], A0, w1.x); fma2(aE[3], A0, w1.y);
      }
    }
    float4 v;
    up2(aE[0], v.x, v.y); up2(aE[1], v.z, v.w);
    *(float4*)(zs + rA * ZSTR + 128 + c0) = v;
    up2(aE[2], v.x, v.y); up2(aE[3], v.z, v.w);
    *(float4*)(zs + rA * ZSTR + 128 + c0 + 4) = v;
  }
  __syncthreads();   // eh visible; WpeS free for Wz reuse

  // --- gates: pre[32x512] = z[32x384] @ Wz + bz, chunks of 16 k ---
  // warp w -> rows 2w, 2w+1 ; lane -> 4 cols per gate (x4 gates)
  const int wrp = tid >> 5;        // 0..15
  const int lane = tid & 31;
  const int zr = wrp * 2;

  u64 ag[2][4][2];
  #pragma unroll
  for (int q = 0; q < 4; q++) {
    ulonglong2 bb = *(const ulonglong2*)(g_bz + q * 128 + lane * 4);
    ag[0][q][0] = bb.x; ag[0][q][1] = bb.y;
    ag[1][q][0] = bb.x; ag[1][q][1] = bb.y;
  }

  // prefetch gate chunk 0: 2048 float4
  #pragma unroll
  for (int j = 0; j < 4; j++) {
    int idx = tid + j * 512;
    int r = idx >> 7, c4 = (idx & 127) * 4;
    cp16(s2u(WzS + r * 512 + c4), g_Wz + r * 512 + c4);
  }
  cpcommit();

  #pragma unroll 1
  for (int ch = 0; ch < 24; ch++) {
    if (ch < 23) {
      int nb = (ch + 1) & 1;
      int k0 = (ch + 1) * 16;
      #pragma unroll
      for (int j = 0; j < 4; j++) {
        int idx = tid + j * 512;
        int r = idx >> 7, c4 = (idx & 127) * 4;
        cp16(s2u(WzS + nb * 8192 + r * 512 + c4), g_Wz + (size_t)(k0 + r) * 512 + c4);
      }
      cpcommit();
      cpwait<1>();
    } else {
      cpwait<0>();
    }
    __syncthreads();
    const float* Wc = WzS + (ch & 1) * 8192;
    const int kb = ch * 16;
    #pragma unroll 1
    for (int kk = 0; kk < 16; kk += 4) {
      float4 z0 = *(const float4*)(zs + (zr + 0) * ZSTR + kb + kk);
      float4 z1 = *(const float4*)(zs + (zr + 1) * ZSTR + kb + kk);
      float c0a[4] = {z0.x, z0.y, z0.z, z0.w};
      float c1a[4] = {z1.x, z1.y, z1.z, z1.w};
      #pragma unroll
      for (int s = 0; s < 4; s++) {
        u64 A0 = bc2(c0a[s]), A1 = bc2(c1a[s]);
        const float* wrow = Wc + (kk + s) * 512 + lane * 4;
        #pragma unroll
        for (int q = 0; q < 4; q++) {
          ulonglong2 w = *(const ulonglong2*)(wrow + q * 128);
          fma2(ag[0][q][0], A0, w.x); fma2(ag[0][q][1], A0, w.y);
          fma2(ag[1][q][0], A1, w.x); fma2(ag[1][q][1], A1, w.y);
        }
      }
    }
    __syncthreads();
  }

  // --- pointwise LSTM (gate order q: 0=i,1=f,2=g,3=o) ---
  {
    const int rowbase = b * N_ + r0 + zr;
    #pragma unroll
    for (int j = 0; j < 2; j++) {
      float pre[4][4];
      #pragma unroll
      for (int q = 0; q < 4; q++) {
        up2(ag[j][q][0], pre[q][0], pre[q][1]);
        up2(ag[j][q][1], pre[q][2], pre[q][3]);
      }
      float* crow = g_c + (size_t)(rowbase + j) * NH_ + lane * 4;
      float4 co = *(const float4*)crow;
      float cin[4] = {co.x, co.y, co.z, co.w};
      float cn[4], hh[4];
      #pragma unroll
      for (int pp = 0; pp < 4; pp++) {
        float iv = fsgm(pre[0][pp]);
        float fv = fsgm(pre[1][pp]);
        float gv = tanhf(pre[2][pp]);
        float ov = fsgm(pre[3][pp]);
        cn[pp] = fv * cin[pp] + iv * gv;
        hh[pp] = ov * tanhf(cn[pp]);
      }
      *(float4*)crow = make_float4(cn[0], cn[1], cn[2], cn[3]);
      float4 hv = make_float4(hh[0], hh[1], hh[2], hh[3]);
      *(float4*)(hnext + (size_t)(rowbase + j) * NH_ + lane * 4) = hv;
      *(float4*)(Hs + (zr + j) * 128 + lane * 4) = hv;
    }
  }
  __syncthreads();

  // --- out[t] = out[t-1] + h @ Wout + bout ; thread: 1 row x 4 cols ---
  {
    const int co0 = (tid & 15) * 4;
    u64 ao[2];
    ulonglong2 bb = *(const ulonglong2*)(p.bout + co0);
    ao[0] = bb.x; ao[1] = bb.y;
    #pragma unroll 4
    for (int k = 0; k < 128; k += 4) {
      float4 av = *(const float4*)(Hs + rA * 128 + k);
      float ac[4] = {av.x, av.y, av.z, av.w};
      #pragma unroll
      for (int s = 0; s < 4; s++) {
        u64 A0 = bc2(ac[s]);
        ulonglong2 w = *(const ulonglong2*)(WoutS + (k + s) * 64 + co0);
        fma2(ao[0], A0, w.x); fma2(ao[1], A0, w.y);
      }
    }
    size_t gb = (size_t)(b * N_ + r0 + rA) * (T_ * NIN_);
    float4 prev = *(const float4*)(p.out + gb + (size_t)(t - 1) * NIN_ + co0);
    float x0, x1, x2, x3;
    up2(ao[0], x0, x1); up2(ao[1], x2, x3);
    *(float4*)(p.out + gb + (size_t)t * NIN_ + co0) =
        make_float4(prev.x + x0, prev.y + x1, prev.z + x2, prev.w + x3);
  }
}

// ---------------- host launch ----------------
extern "C" void kernel_launch(void* const* d_in, const int* in_sizes, int n_in,
                              void* d_out, int out_size) {
  const float* X   = (const float*)d_in[0];
  const float* A   = (const float*)d_in[1];
  const float* Wse = (const float*)d_in[2];
  const float* bse = (const float*)d_in[3];
  StepP p;
  p.Wpe  = (const float*)d_in[4];  p.bpe  = (const float*)d_in[5];
  p.Wii  = (const float*)d_in[6];  p.bii  = (const float*)d_in[7];
  p.Whi  = (const float*)d_in[8];  p.bhi  = (const float*)d_in[9];
  p.Wif  = (const float*)d_in[10]; p.bif  = (const float*)d_in[11];
  p.Whf  = (const float*)d_in[12]; p.bhf  = (const float*)d_in[13];
  p.Wig  = (const float*)d_in[14]; p.big  = (const float*)d_in[15];
  p.Whg  = (const float*)d_in[16]; p.bhg  = (const float*)d_in[17];
  p.Wio  = (const float*)d_in[18]; p.bio  = (const float*)d_in[19];
  p.Who  = (const float*)d_in[20]; p.bho  = (const float*)d_in[21];
  p.Wout = (const float*)d_in[22]; p.bout = (const float*)d_in[23];
  p.out  = (float*)d_out;

  const int SMEM = SM_TOTF * 4;  // 214,016 B
  cudaFuncSetAttribute(k_step, cudaFuncAttributeMaxDynamicSharedMemorySize, SMEM);

  k_dinv<<<ROWS_, 128>>>(A);
  k_an<<<2048, 256>>>(A);
  k_fuse<<<768, 256>>>(p);
  k_init<<<2048, 256>>>(X, Wse, bse, p.out);
  for (int t = 1; t < T_; t++) {
    k_step<<<dim3(N_ / 32, B_), 512, SMEM>>>(p, t);
  }
}

// round 10
// speedup vs baseline: 2.2687x; 2.2687x over previous
#include <cuda_runtime.h>
#include <math.h>
#include <stdint.h>

#define B_    8
#define N_    512
#define T_    64
#define NIN_  64
#define NEMB_ 128
#define NH_   128
#define ROWS_ (B_ * N_)
#define ZSTR  392   // padded z row stride (floats)

typedef unsigned long long u64;

// ---------------- device scratch ----------------
__device__ float g_An[B_ * N_ * N_];
__device__ float g_dinv[ROWS_];
__device__ float g_es[ROWS_ * NEMB_];
__device__ float g_h[2][ROWS_ * NH_];
__device__ float g_c[ROWS_ * NH_];
__device__ float g_Wz[384 * 512];   // fused gate weights: rows 0:128 es | 128:256 folded Wpe@Wz_eh | 256:384 h
__device__ float g_bz[512];         // fused gate bias (incl. bpe@Wz_eh fold)

// ---------------- packed f32x2 helpers ----------------
__device__ __forceinline__ u64 pk2(float x, float y) {
  u64 r; asm("mov.b64 %0, {%1, %2};" : "=l"(r) : "f"(x), "f"(y)); return r;
}
__device__ __forceinline__ u64 bc2(float x) { return pk2(x, x); }
__device__ __forceinline__ void up2(u64 v, float& x, float& y) {
  asm("mov.b64 {%0, %1}, %2;" : "=f"(x), "=f"(y) : "l"(v));
}
__device__ __forceinline__ void fma2(u64& d, u64 a, u64 b) {
  asm("fma.rn.f32x2 %0, %1, %2, %0;" : "+l"(d) : "l"(a), "l"(b));
}
// fast sigmoid (ex2/rcp approx: ~1e-7 err). tanh stays accurate (tanhf).
__device__ __forceinline__ float fsgm(float x) {
  float e; asm("ex2.approx.f32 %0, %1;" : "=f"(e) : "f"(-1.4426950408889634f * x));
  float r; asm("rcp.approx.f32 %0, %1;" : "=f"(r) : "f"(1.0f + e));
  return r;
}
// cp.async
__device__ __forceinline__ uint32_t s2u(const void* p) {
  return (uint32_t)__cvta_generic_to_shared(p);
}
__device__ __forceinline__ void cp16(uint32_t d, const void* s) {
  asm volatile("cp.async.cg.shared.global [%0], [%1], 16;\n" :: "r"(d), "l"(s));
}
__device__ __forceinline__ void cpcommit() { asm volatile("cp.async.commit_group;\n"); }
template <int N> __device__ __forceinline__ void cpwait() {
  asm volatile("cp.async.wait_group %0;\n" :: "n"(N));
}

// ---------------- preamble kernels ----------------
__global__ void k_dinv(const float* __restrict__ A) {
  int row = blockIdx.x;
  const float* ap = A + (size_t)row * N_;
  float s = 0.0f;
  for (int m = threadIdx.x; m < N_; m += blockDim.x) s += ap[m];
  __shared__ float red[128];
  red[threadIdx.x] = s;
  __syncthreads();
  for (int off = 64; off; off >>= 1) {
    if (threadIdx.x < off) red[threadIdx.x] += red[threadIdx.x + off];
    __syncthreads();
  }
  if (threadIdx.x == 0) {
    float d = red[0];
    g_dinv[row] = (d > 0.0f) ? (1.0f / sqrtf(d)) : 0.0f;
  }
}

__global__ void k_an(const float* __restrict__ A) {
  size_t total = (size_t)B_ * N_ * N_;
  for (size_t i = blockIdx.x * (size_t)blockDim.x + threadIdx.x; i < total;
       i += (size_t)gridDim.x * blockDim.x) {
    int m = (int)(i & 511);
    size_t r = i >> 9;
    int n = (int)(r & 511);
    int b = (int)(r >> 9);
    g_An[i] = A[i] * g_dinv[b * N_ + n] * g_dinv[b * N_ + m];
  }
}

__global__ void k_init(const float* __restrict__ X, const float* __restrict__ Wse,
                       const float* __restrict__ bse, float* __restrict__ out) {
  int tid = blockIdx.x * blockDim.x + threadIdx.x;
  int row = tid >> 7;
  int c = tid & 127;
  const float* x0 = X + (size_t)row * (T_ * NIN_);
  float acc = bse[c];
  #pragma unroll 8
  for (int k = 0; k < NIN_; k++) acc += x0[k] * Wse[k * NEMB_ + c];
  g_es[(size_t)row * NEMB_ + c] = acc;
  g_h[0][tid] = 0.0f;
  g_c[tid] = 0.0f;
  if (c < NIN_) out[(size_t)row * (T_ * NIN_) + c] = x0[c];
}

struct StepP {
  const float *Wpe, *bpe, *Wii, *bii, *Whi, *bhi, *Wif, *bif, *Whf, *bhf,
              *Wig, *big, *Whg, *bhg, *Wio, *bio, *Who, *bho, *Wout, *bout;
  float* out;
};

// Build fused gate matrix with the eh-projection folded in:
//   rows 0:128   -> Wx rows 0:128        (es part)
//   rows 128:256 -> Wpe @ Wx[128:256]    (H part, eh folded)
//   rows 256:384 -> Wh                   (h part)
//   bias          = bx + bh + bpe @ Wx[128:256]
__global__ void k_fuse(StepP p) {
  int i = blockIdx.x * blockDim.x + threadIdx.x;
  if (i < 384 * 512) {
    int c = i & 511, r = i >> 9, q = c >> 7, cc = c & 127;
    const float* Wx = q == 0 ? p.Wii : q == 1 ? p.Wif : q == 2 ? p.Wig : p.Wio;
    const float* Wh = q == 0 ? p.Whi : q == 1 ? p.Whf : q == 2 ? p.Whg : p.Who;
    float v;
    if (r < 128) {
      v = Wx[r * 128 + cc];
    } else if (r < 256) {
      int j = r - 128;
      float s = 0.0f;
      #pragma unroll 4
      for (int m = 0; m < 128; m++)
        s += p.Wpe[j * 128 + m] * Wx[(128 + m) * 128 + cc];
      v = s;
    } else {
      v = Wh[(r - 256) * 128 + cc];
    }
    g_Wz[i] = v;
  }
  if (i < 512) {
    int q = i >> 7, cc = i & 127;
    const float* Wx = q == 0 ? p.Wii : q == 1 ? p.Wif : q == 2 ? p.Wig : p.Wio;
    const float* bx = q == 0 ? p.bii : q == 1 ? p.bif : q == 2 ? p.big : p.bio;
    const float* bh = q == 0 ? p.bhi : q == 1 ? p.bhf : q == 2 ? p.bhg : p.bho;
    float s = bx[cc] + bh[cc];
    #pragma unroll 4
    for (int m = 0; m < 128; m++)
      s += p.bpe[m] * Wx[(128 + m) * 128 + cc];
    g_bz[i] = s;
  }
}

// ---------------- step kernel (256 threads, R6 structure, eh phase removed) ----
// smem float offsets
#define SM_ZS   0                  // 32 x ZSTR = 12544  (0:128 es | 128:256 H | 256:384 h_prev)
#define SM_HS   12544              // 32 x 128  = 4096   (h_t for Wout)
#define SM_BUFA 16640              // hs[2][64*128]=16384 + As[2][32*64]=4096 ; later Wout[128*64]=8192
#define SM_BUFB 37120              // Wz[2][16*512]=16384
#define SM_TOTF 53504              // floats (214,016 B)

__global__ void __launch_bounds__(256, 1) k_step(StepP p, int t) {
  extern __shared__ float sm[];
  float* zs    = sm + SM_ZS;
  float* Hs    = sm + SM_HS;
  float* hsbuf = sm + SM_BUFA;              // [2][64*128]
  float* Asbuf = sm + SM_BUFA + 16384;      // [2][32*64]
  float* WoutS = sm + SM_BUFA;              // [128][64] (aliases hsbuf after GEMM1)
  float* WzS   = sm + SM_BUFB;              // [2][16*512]

  const float* hprev = g_h[(t - 1) & 1];
  float* hnext = g_h[t & 1];

  const int b = blockIdx.y;
  const int r0 = blockIdx.x * 32;
  const int tid = threadIdx.x;

  const float* esb = g_es + (size_t)(b * N_ + r0) * NEMB_;
  const float* hpb = hprev + (size_t)b * N_ * NH_;
  const float* hpr = hpb + (size_t)r0 * NH_;
  const float* Anb = g_An + (size_t)(b * N_ + r0) * N_;

  // --- group 1: zs (es + h_prev slice) ---
  #pragma unroll
  for (int j = 0; j < 4; j++) {
    int idx = tid + j * 256;
    int r = idx >> 5, c4 = (idx & 31) * 4;
    cp16(s2u(zs + r * ZSTR + c4), esb + r * NEMB_ + c4);
    cp16(s2u(zs + r * ZSTR + 256 + c4), hpr + r * NH_ + c4);
  }
  cpcommit();

  // --- GEMM1: H[32x128] = An_tile @ h_prev, K=512, chunks of 64 ---
  const int rA = tid >> 4, rB = (tid >> 4) + 16;
  const int cblk = tid & 15;

  // prefetch chunk 0
  {
    #pragma unroll
    for (int j = 0; j < 8; j++) {
      int idx = tid + j * 256;
      int r = idx >> 5, c4 = (idx & 31) * 4;
      cp16(s2u(hsbuf + r * 128 + c4), hpb + (size_t)r * NH_ + c4);
    }
    #pragma unroll
    for (int j = 0; j < 2; j++) {
      int idx = tid + j * 256;
      int r = idx >> 4, k4 = (idx & 15) * 4;
      cp16(s2u(Asbuf + r * 64 + k4), Anb + (size_t)r * N_ + k4);
    }
  }
  cpcommit();

  u64 aH[2][2][2];
  #pragma unroll
  for (int i = 0; i < 2; i++)
    #pragma unroll
    for (int j = 0; j < 2; j++) { aH[i][j][0] = 0ull; aH[i][j][1] = 0ull; }

  #pragma unroll 1
  for (int ch = 0; ch < 8; ch++) {
    if (ch < 7) {
      int nb = (ch + 1) & 1;
      int k0 = (ch + 1) * 64;
      #pragma unroll
      for (int j = 0; j < 8; j++) {
        int idx = tid + j * 256;
        int r = idx >> 5, c4 = (idx & 31) * 4;
        cp16(s2u(hsbuf + nb * 8192 + r * 128 + c4), hpb + (size_t)(k0 + r) * NH_ + c4);
      }
      #pragma unroll
      for (int j = 0; j < 2; j++) {
        int idx = tid + j * 256;
        int r = idx >> 4, k4 = (idx & 15) * 4;
        cp16(s2u(Asbuf + nb * 2048 + r * 64 + k4), Anb + (size_t)r * N_ + k0 + k4);
      }
      cpcommit();
      cpwait<1>();
    } else {
      cpwait<0>();
    }
    __syncthreads();
    const float* hc = hsbuf + (ch & 1) * 8192;
    const float* Ac = Asbuf + (ch & 1) * 2048;
    #pragma unroll 4
    for (int kk = 0; kk < 64; kk += 4) {
      float4 a0v = *(const float4*)(Ac + rA * 64 + kk);
      float4 a1v = *(const float4*)(Ac + rB * 64 + kk);
      float a0c[4] = {a0v.x, a0v.y, a0v.z, a0v.w};
      float a1c[4] = {a1v.x, a1v.y, a1v.z, a1v.w};
      #pragma unroll
      for (int s = 0; s < 4; s++) {
        u64 A0 = bc2(a0c[s]), A1 = bc2(a1c[s]);
        const float* hrow = hc + (kk + s) * 128 + cblk * 4;
        ulonglong2 w0 = *(const ulonglong2*)(hrow);
        ulonglong2 w1 = *(const ulonglong2*)(hrow + 64);
        fma2(aH[0][0][0], A0, w0.x); fma2(aH[0][0][1], A0, w0.y);
        fma2(aH[0][1][0], A0, w1.x); fma2(aH[0][1][1], A0, w1.y);
        fma2(aH[1][0][0], A1, w0.x); fma2(aH[1][0][1], A1, w0.y);
        fma2(aH[1][1][0], A1, w1.x); fma2(aH[1][1][1], A1, w1.y);
      }
    }
    __syncthreads();
  }

  // store H directly into z (cols 128:256) — eh is folded into Wz
  {
    float4 v;
    up2(aH[0][0][0], v.x, v.y); up2(aH[0][0][1], v.z, v.w);
    *(float4*)(zs + rA * ZSTR + 128 + cblk * 4) = v;
    up2(aH[0][1][0], v.x, v.y); up2(aH[0][1][1], v.z, v.w);
    *(float4*)(zs + rA * ZSTR + 192 + cblk * 4) = v;
    up2(aH[1][0][0], v.x, v.y); up2(aH[1][0][1], v.z, v.w);
    *(float4*)(zs + rB * ZSTR + 128 + cblk * 4) = v;
    up2(aH[1][1][0], v.x, v.y); up2(aH[1][1][1], v.z, v.w);
    *(float4*)(zs + rB * ZSTR + 192 + cblk * 4) = v;
  }
  // prefetch Wout into bufA (GEMM1 done with it)
  #pragma unroll
  for (int j = 0; j < 8; j++) {
    int idx = tid + j * 256;
    int r = idx >> 4, c4 = (idx & 15) * 4;
    cp16(s2u(WoutS + r * 64 + c4), p.Wout + r * 64 + c4);
  }
  cpcommit();

  // --- gates: pre[32x512] = z[32x384] @ Wz + bz, chunks of 16 k ---
  const int rowg = tid >> 5;       // warp id: 8 warps x 4 rows
  const int colg = tid & 31;       // lane: 4 cols per gate
  const int zr = rowg * 4;

  u64 ag[4][4][2];
  #pragma unroll
  for (int q = 0; q < 4; q++) {
    ulonglong2 bb = *(const ulonglong2*)(g_bz + q * 128 + colg * 4);
    #pragma unroll
    for (int j = 0; j < 4; j++) { ag[j][q][0] = bb.x; ag[j][q][1] = bb.y; }
  }

  // prefetch gate chunk 0
  #pragma unroll
  for (int j = 0; j < 8; j++) {
    int idx = tid + j * 256;
    int r = idx >> 7, c4 = (idx & 127) * 4;
    cp16(s2u(WzS + r * 512 + c4), g_Wz + r * 512 + c4);
  }
  cpcommit();

  #pragma unroll 1
  for (int ch = 0; ch < 24; ch++) {
    if (ch < 23) {
      int nb = (ch + 1) & 1;
      int k0 = (ch + 1) * 16;
      #pragma unroll
      for (int j = 0; j < 8; j++) {
        int idx = tid + j * 256;
        int r = idx >> 7, c4 = (idx & 127) * 4;
        cp16(s2u(WzS + nb * 8192 + r * 512 + c4), g_Wz + (size_t)(k0 + r) * 512 + c4);
      }
      cpcommit();
      cpwait<1>();
    } else {
      cpwait<0>();
    }
    __syncthreads();
    const float* Wc = WzS + (ch & 1) * 8192;
    const int kb = ch * 16;
    #pragma unroll 1
    for (int kk = 0; kk < 16; kk += 4) {
      float4 z0 = *(const float4*)(zs + (zr + 0) * ZSTR + kb + kk);
      float4 z1 = *(const float4*)(zs + (zr + 1) * ZSTR + kb + kk);
      float4 z2 = *(const float4*)(zs + (zr + 2) * ZSTR + kb + kk);
      float4 z3 = *(const float4*)(zs + (zr + 3) * ZSTR + kb + kk);
      float c0a[4] = {z0.x, z0.y, z0.z, z0.w};
      float c1a[4] = {z1.x, z1.y, z1.z, z1.w};
      float c2a[4] = {z2.x, z2.y, z2.z, z2.w};
      float c3a[4] = {z3.x, z3.y, z3.z, z3.w};
      #pragma unroll
      for (int s = 0; s < 4; s++) {
        u64 A0 = bc2(c0a[s]), A1 = bc2(c1a[s]), A2 = bc2(c2a[s]), A3 = bc2(c3a[s]);
        const float* wrow = Wc + (kk + s) * 512 + colg * 4;
        #pragma unroll
        for (int q = 0; q < 4; q++) {
          ulonglong2 w = *(const ulonglong2*)(wrow + q * 128);
          fma2(ag[0][q][0], A0, w.x); fma2(ag[0][q][1], A0, w.y);
          fma2(ag[1][q][0], A1, w.x); fma2(ag[1][q][1], A1, w.y);
          fma2(ag[2][q][0], A2, w.x); fma2(ag[2][q][1], A2, w.y);
          fma2(ag[3][q][0], A3, w.x); fma2(ag[3][q][1], A3, w.y);
        }
      }
    }
    __syncthreads();
  }

  // --- pointwise LSTM (gate order q: 0=i,1=f,2=g,3=o) ---
  {
    const int rowbase = b * N_ + r0 + zr;
    #pragma unroll
    for (int j = 0; j < 4; j++) {
      float pre[4][4];
      #pragma unroll
      for (int q = 0; q < 4; q++) {
        up2(ag[j][q][0], pre[q][0], pre[q][1]);
        up2(ag[j][q][1], pre[q][2], pre[q][3]);
      }
      float* crow = g_c + (size_t)(rowbase + j) * NH_ + colg * 4;
      float4 co = *(const float4*)crow;
      float cin[4] = {co.x, co.y, co.z, co.w};
      float cn[4], hh[4];
      #pragma unroll
      for (int pp = 0; pp < 4; pp++) {
        float iv = fsgm(pre[0][pp]);
        float fv = fsgm(pre[1][pp]);
        float gv = tanhf(pre[2][pp]);
        float ov = fsgm(pre[3][pp]);
        cn[pp] = fv * cin[pp] + iv * gv;
        hh[pp] = ov * tanhf(cn[pp]);
      }
      *(float4*)crow = make_float4(cn[0], cn[1], cn[2], cn[3]);
      float4 hv = make_float4(hh[0], hh[1], hh[2], hh[3]);
      *(float4*)(hnext + (size_t)(rowbase + j) * NH_ + colg * 4) = hv;
      *(float4*)(Hs + (zr + j) * 128 + colg * 4) = hv;
    }
  }
  __syncthreads();

  // --- out[t] = out[t-1] + h @ Wout + bout ---
  {
    int co0 = cblk * 4;
    const ulonglong2* bp = (const ulonglong2*)(p.bout + co0);
    ulonglong2 bb = bp[0];
    u64 oa00 = bb.x, oa01 = bb.y, oa10 = bb.x, oa11 = bb.y;
    #pragma unroll 4
    for (int k = 0; k < NH_; k += 4) {
      float4 a0v = *(const float4*)(Hs + rA * 128 + k);
      float4 a1v = *(const float4*)(Hs + rB * 128 + k);
      float a0c[4] = {a0v.x, a0v.y, a0v.z, a0v.w};
      float a1c[4] = {a1v.x, a1v.y, a1v.z, a1v.w};
      #pragma unroll
      for (int s = 0; s < 4; s++) {
        u64 A0 = bc2(a0c[s]), A1 = bc2(a1c[s]);
        ulonglong2 w = *(const ulonglong2*)(WoutS + (k + s) * 64 + co0);
        fma2(oa00, A0, w.x); fma2(oa01, A0, w.y);
        fma2(oa10, A1, w.x); fma2(oa11, A1, w.y);
      }
    }
    #pragma unroll
    for (int rr = 0; rr < 2; rr++) {
      int r = (rr ? rB : rA);
      size_t gb = (size_t)(b * N_ + r0 + r) * (T_ * NIN_);
      float4 prev = *(const float4*)(p.out + gb + (size_t)(t - 1) * NIN_ + co0);
      float x0, x1, x2, x3;
      if (rr == 0) { up2(oa00, x0, x1); up2(oa01, x2, x3); }
      else         { up2(oa10, x0, x1); up2(oa11, x2, x3); }
      float4 nw = make_float4(prev.x + x0, prev.y + x1, prev.z + x2, prev.w + x3);
      *(float4*)(p.out + gb + (size_t)t * NIN_ + co0) = nw;
    }
  }
}

// ---------------- host launch ----------------
extern "C" void kernel_launch(void* const* d_in, const int* in_sizes, int n_in,
                              void* d_out, int out_size) {
  const float* X   = (const float*)d_in[0];
  const float* A   = (const float*)d_in[1];
  const float* Wse = (const float*)d_in[2];
  const float* bse = (const float*)d_in[3];
  StepP p;
  p.Wpe  = (const float*)d_in[4];  p.bpe  = (const float*)d_in[5];
  p.Wii  = (const float*)d_in[6];  p.bii  = (const float*)d_in[7];
  p.Whi  = (const float*)d_in[8];  p.bhi  = (const float*)d_in[9];
  p.Wif  = (const float*)d_in[10]; p.bif  = (const float*)d_in[11];
  p.Whf  = (const float*)d_in[12]; p.bhf  = (const float*)d_in[13];
  p.Wig  = (const float*)d_in[14]; p.big  = (const float*)d_in[15];
  p.Whg  = (const float*)d_in[16]; p.bhg  = (const float*)d_in[17];
  p.Wio  = (const float*)d_in[18]; p.bio  = (const float*)d_in[19];
  p.Who  = (const float*)d_in[20]; p.bho  = (const float*)d_in[21];
  p.Wout = (const float*)d_in[22]; p.bout = (const float*)d_in[23];
  p.out  = (float*)d_out;

  const int SMEM = SM_TOTF * 4;  // 214,016 B
  cudaFuncSetAttribute(k_step, cudaFuncAttributeMaxDynamicSharedMemorySize, SMEM);

  k_dinv<<<ROWS_, 128>>>(A);
  k_an<<<2048, 256>>>(A);
  k_fuse<<<768, 256>>>(p);
  k_init<<<2048, 256>>>(X, Wse, bse, p.out);
  for (int t = 1; t < T_; t++) {
    k_step<<<dim3(N_ / 32, B_), 256, SMEM>>>(p, t);
  }
}

// round 11
// speedup vs baseline: 2.3514x; 1.0365x over previous
#include <cuda_runtime.h>
#include <math.h>
#include <stdint.h>

#define B_    8
#define N_    512
#define T_    64
#define NIN_  64
#define NEMB_ 128
#define NH_   128
#define ROWS_ (B_ * N_)
#define ZSTR  392   // padded z row stride (floats)

typedef unsigned long long u64;

// ---------------- device scratch ----------------
__device__ float g_An[B_ * N_ * N_];
__device__ float g_dinv[ROWS_];
__device__ float g_es[ROWS_ * NEMB_];
__device__ float g_h[2][ROWS_ * NH_];
__device__ float g_c[ROWS_ * NH_];
__device__ float g_Wz[384 * 512];   // fused gate weights: rows 0:128 es | 128:256 folded Wpe@Wz_eh | 256:384 h
__device__ float g_bz[512];         // fused gate bias (incl. bpe@Wz_eh fold)

// ---------------- packed f32x2 helpers ----------------
__device__ __forceinline__ u64 pk2(float x, float y) {
  u64 r; asm("mov.b64 %0, {%1, %2};" : "=l"(r) : "f"(x), "f"(y)); return r;
}
__device__ __forceinline__ u64 bc2(float x) { return pk2(x, x); }
__device__ __forceinline__ void up2(u64 v, float& x, float& y) {
  asm("mov.b64 {%0, %1}, %2;" : "=f"(x), "=f"(y) : "l"(v));
}
__device__ __forceinline__ void fma2(u64& d, u64 a, u64 b) {
  asm("fma.rn.f32x2 %0, %1, %2, %0;" : "+l"(d) : "l"(a), "l"(b));
}
// fast sigmoid (ex2/rcp approx: ~1e-7 err). tanh stays accurate (tanhf).
__device__ __forceinline__ float fsgm(float x) {
  float e; asm("ex2.approx.f32 %0, %1;" : "=f"(e) : "f"(-1.4426950408889634f * x));
  float r; asm("rcp.approx.f32 %0, %1;" : "=f"(r) : "f"(1.0f + e));
  return r;
}
// cp.async
__device__ __forceinline__ uint32_t s2u(const void* p) {
  return (uint32_t)__cvta_generic_to_shared(p);
}
__device__ __forceinline__ void cp16(uint32_t d, const void* s) {
  asm volatile("cp.async.cg.shared.global [%0], [%1], 16;\n" :: "r"(d), "l"(s));
}
__device__ __forceinline__ void cpcommit() { asm volatile("cp.async.commit_group;\n"); }
template <int N> __device__ __forceinline__ void cpwait() {
  asm volatile("cp.async.wait_group %0;\n" :: "n"(N));
}

// ---------------- preamble kernels ----------------
__global__ void k_dinv(const float* __restrict__ A) {
  int row = blockIdx.x;
  const float* ap = A + (size_t)row * N_;
  float s = 0.0f;
  for (int m = threadIdx.x; m < N_; m += blockDim.x) s += ap[m];
  __shared__ float red[128];
  red[threadIdx.x] = s;
  __syncthreads();
  for (int off = 64; off; off >>= 1) {
    if (threadIdx.x < off) red[threadIdx.x] += red[threadIdx.x + off];
    __syncthreads();
  }
  if (threadIdx.x == 0) {
    float d = red[0];
    g_dinv[row] = (d > 0.0f) ? (1.0f / sqrtf(d)) : 0.0f;
  }
}

__global__ void k_an(const float* __restrict__ A) {
  size_t total = (size_t)B_ * N_ * N_;
  for (size_t i = blockIdx.x * (size_t)blockDim.x + threadIdx.x; i < total;
       i += (size_t)gridDim.x * blockDim.x) {
    int m = (int)(i & 511);
    size_t r = i >> 9;
    int n = (int)(r & 511);
    int b = (int)(r >> 9);
    g_An[i] = A[i] * g_dinv[b * N_ + n] * g_dinv[b * N_ + m];
  }
}

__global__ void k_init(const float* __restrict__ X, const float* __restrict__ Wse,
                       const float* __restrict__ bse, float* __restrict__ out) {
  int tid = blockIdx.x * blockDim.x + threadIdx.x;
  int row = tid >> 7;
  int c = tid & 127;
  const float* x0 = X + (size_t)row * (T_ * NIN_);
  float acc = bse[c];
  #pragma unroll 8
  for (int k = 0; k < NIN_; k++) acc += x0[k] * Wse[k * NEMB_ + c];
  g_es[(size_t)row * NEMB_ + c] = acc;
  g_h[0][tid] = 0.0f;
  g_c[tid] = 0.0f;
  if (c < NIN_) out[(size_t)row * (T_ * NIN_) + c] = x0[c];
}

struct StepP {
  const float *Wpe, *bpe, *Wii, *bii, *Whi, *bhi, *Wif, *bif, *Whf, *bhf,
              *Wig, *big, *Whg, *bhg, *Wio, *bio, *Who, *bho, *Wout, *bout;
  float* out;
};

// Fused gate matrix with eh-projection folded in (see R9).
__global__ void k_fuse(StepP p) {
  int i = blockIdx.x * blockDim.x + threadIdx.x;
  if (i < 384 * 512) {
    int c = i & 511, r = i >> 9, q = c >> 7, cc = c & 127;
    const float* Wx = q == 0 ? p.Wii : q == 1 ? p.Wif : q == 2 ? p.Wig : p.Wio;
    const float* Wh = q == 0 ? p.Whi : q == 1 ? p.Whf : q == 2 ? p.Whg : p.Who;
    float v;
    if (r < 128) {
      v = Wx[r * 128 + cc];
    } else if (r < 256) {
      int j = r - 128;
      float s = 0.0f;
      #pragma unroll 4
      for (int m = 0; m < 128; m++)
        s += p.Wpe[j * 128 + m] * Wx[(128 + m) * 128 + cc];
      v = s;
    } else {
      v = Wh[(r - 256) * 128 + cc];
    }
    g_Wz[i] = v;
  }
  if (i < 512) {
    int q = i >> 7, cc = i & 127;
    const float* Wx = q == 0 ? p.Wii : q == 1 ? p.Wif : q == 2 ? p.Wig : p.Wio;
    const float* bx = q == 0 ? p.bii : q == 1 ? p.bif : q == 2 ? p.big : p.bio;
    const float* bh = q == 0 ? p.bhi : q == 1 ? p.bhf : q == 2 ? p.bhg : p.bho;
    float s = bx[cc] + bh[cc];
    #pragma unroll 4
    for (int m = 0; m < 128; m++)
      s += p.bpe[m] * Wx[(128 + m) * 128 + cc];
    g_bz[i] = s;
  }
}

// ---------------- step kernel (256 threads, mega-chunks) ----------------
// smem float offsets:
//   zs [0, 12544)          32 x ZSTR  (0:128 es, later h_t | 128:256 H | 256:384 h_prev)
//   X  [12544, 45312)      32768 floats: GEMM1 h buf [2][128*128] ; gates Wz buf [2][32*512]
//   Y  [45312, 53504)      8192 floats:  GEMM1 A buf [2][32*128]  ; Wout [128*64]
#define SM_ZS   0
#define SM_X    12544
#define SM_Y    45312
#define SM_TOTF 53504              // 214,016 B

__global__ void __launch_bounds__(256, 1) k_step(StepP p, int t) {
  extern __shared__ float sm[];
  float* zs = sm + SM_ZS;
  float* Xb = sm + SM_X;    // chunk buffers (16384 floats per buf)
  float* Yb = sm + SM_Y;    // A tiles (4096 per buf) / WoutS

  const float* hprev = g_h[(t - 1) & 1];
  float* hnext = g_h[t & 1];

  const int b = blockIdx.y;
  const int r0 = blockIdx.x * 32;
  const int tid = threadIdx.x;

  const float* esb = g_es + (size_t)(b * N_ + r0) * NEMB_;
  const float* hpb = hprev + (size_t)b * N_ * NH_;
  const float* hpr = hpb + (size_t)r0 * NH_;
  const float* Anb = g_An + (size_t)(b * N_ + r0) * N_;

  // --- group: zs (es + h_prev slice) ---
  #pragma unroll
  for (int j = 0; j < 4; j++) {
    int idx = tid + j * 256;
    int r = idx >> 5, c4 = (idx & 31) * 4;
    cp16(s2u(zs + r * ZSTR + c4), esb + r * NEMB_ + c4);
    cp16(s2u(zs + r * ZSTR + 256 + c4), hpr + r * NH_ + c4);
  }
  cpcommit();

  // --- GEMM1: H[32x128] = An_tile @ h_prev, K=512, chunks of 128 ---
  const int rA = tid >> 4, rB = (tid >> 4) + 16;
  const int cblk = tid & 15;

  // prefetch chunk 0 (h rows 0..127, A cols 0..127)
  {
    #pragma unroll
    for (int j = 0; j < 16; j++) {
      int idx = tid + j * 256;
      int r = idx >> 5, c4 = (idx & 31) * 4;
      cp16(s2u(Xb + r * 128 + c4), hpb + (size_t)r * NH_ + c4);
    }
    #pragma unroll
    for (int j = 0; j < 4; j++) {
      int idx = tid + j * 256;
      int r = idx >> 5, k4 = (idx & 31) * 4;
      cp16(s2u(Yb + r * 128 + k4), Anb + (size_t)r * N_ + k4);
    }
  }
  cpcommit();

  u64 aH[2][2][2];
  #pragma unroll
  for (int i = 0; i < 2; i++)
    #pragma unroll
    for (int j = 0; j < 2; j++) { aH[i][j][0] = 0ull; aH[i][j][1] = 0ull; }

  #pragma unroll 1
  for (int ch = 0; ch < 4; ch++) {
    if (ch < 3) {
      int nb = (ch + 1) & 1;
      int k0 = (ch + 1) * 128;
      #pragma unroll
      for (int j = 0; j < 16; j++) {
        int idx = tid + j * 256;
        int r = idx >> 5, c4 = (idx & 31) * 4;
        cp16(s2u(Xb + nb * 16384 + r * 128 + c4), hpb + (size_t)(k0 + r) * NH_ + c4);
      }
      #pragma unroll
      for (int j = 0; j < 4; j++) {
        int idx = tid + j * 256;
        int r = idx >> 5, k4 = (idx & 31) * 4;
        cp16(s2u(Yb + nb * 4096 + r * 128 + k4), Anb + (size_t)r * N_ + k0 + k4);
      }
      cpcommit();
      cpwait<1>();
    } else {
      cpwait<0>();
    }
    __syncthreads();
    const float* hc = Xb + (ch & 1) * 16384;
    const float* Ac = Yb + (ch & 1) * 4096;
    #pragma unroll 4
    for (int kk = 0; kk < 128; kk += 4) {
      float4 a0v = *(const float4*)(Ac + rA * 128 + kk);
      float4 a1v = *(const float4*)(Ac + rB * 128 + kk);
      float a0c[4] = {a0v.x, a0v.y, a0v.z, a0v.w};
      float a1c[4] = {a1v.x, a1v.y, a1v.z, a1v.w};
      #pragma unroll
      for (int s = 0; s < 4; s++) {
        u64 A0 = bc2(a0c[s]), A1 = bc2(a1c[s]);
        const float* hrow = hc + (kk + s) * 128 + cblk * 4;
        ulonglong2 w0 = *(const ulonglong2*)(hrow);
        ulonglong2 w1 = *(const ulonglong2*)(hrow + 64);
        fma2(aH[0][0][0], A0, w0.x); fma2(aH[0][0][1], A0, w0.y);
        fma2(aH[0][1][0], A0, w1.x); fma2(aH[0][1][1], A0, w1.y);
        fma2(aH[1][0][0], A1, w0.x); fma2(aH[1][0][1], A1, w0.y);
        fma2(aH[1][1][0], A1, w1.x); fma2(aH[1][1][1], A1, w1.y);
      }
    }
    __syncthreads();
  }

  // store H directly into z (cols 128:256) — eh is folded into Wz
  {
    float4 v;
    up2(aH[0][0][0], v.x, v.y); up2(aH[0][0][1], v.z, v.w);
    *(float4*)(zs + rA * ZSTR + 128 + cblk * 4) = v;
    up2(aH[0][1][0], v.x, v.y); up2(aH[0][1][1], v.z, v.w);
    *(float4*)(zs + rA * ZSTR + 192 + cblk * 4) = v;
    up2(aH[1][0][0], v.x, v.y); up2(aH[1][0][1], v.z, v.w);
    *(float4*)(zs + rB * ZSTR + 128 + cblk * 4) = v;
    up2(aH[1][1][0], v.x, v.y); up2(aH[1][1][1], v.z, v.w);
    *(float4*)(zs + rB * ZSTR + 192 + cblk * 4) = v;
  }
  // prefetch Wout into Y (GEMM1 done with it)
  #pragma unroll
  for (int j = 0; j < 8; j++) {
    int idx = tid + j * 256;
    int r = idx >> 4, c4 = (idx & 15) * 4;
    cp16(s2u(Yb + r * 64 + c4), p.Wout + r * 64 + c4);
  }
  cpcommit();

  // --- gates: pre[32x512] = z[32x384] @ Wz + bz, chunks of 32 k ---
  const int rowg = tid >> 5;       // warp id: 8 warps x 4 rows
  const int colg = tid & 31;       // lane: 4 cols per gate
  const int zr = rowg * 4;

  u64 ag[4][4][2];
  #pragma unroll
  for (int q = 0; q < 4; q++) {
    ulonglong2 bb = *(const ulonglong2*)(g_bz + q * 128 + colg * 4);
    #pragma unroll
    for (int j = 0; j < 4; j++) { ag[j][q][0] = bb.x; ag[j][q][1] = bb.y; }
  }

  // prefetch gate chunk 0 (32 rows of Wz)
  #pragma unroll
  for (int j = 0; j < 16; j++) {
    int idx = tid + j * 256;
    int r = idx >> 7, c4 = (idx & 127) * 4;
    cp16(s2u(Xb + r * 512 + c4), g_Wz + r * 512 + c4);
  }
  cpcommit();

  #pragma unroll 1
  for (int ch = 0; ch < 12; ch++) {
    if (ch < 11) {
      int nb = (ch + 1) & 1;
      int k0 = (ch + 1) * 32;
      #pragma unroll
      for (int j = 0; j < 16; j++) {
        int idx = tid + j * 256;
        int r = idx >> 7, c4 = (idx & 127) * 4;
        cp16(s2u(Xb + nb * 16384 + r * 512 + c4), g_Wz + (size_t)(k0 + r) * 512 + c4);
      }
      cpcommit();
      cpwait<1>();
    } else {
      cpwait<0>();
    }
    __syncthreads();
    const float* Wc = Xb + (ch & 1) * 16384;
    const int kb = ch * 32;
    #pragma unroll 1
    for (int kk = 0; kk < 32; kk += 4) {
      float4 z0 = *(const float4*)(zs + (zr + 0) * ZSTR + kb + kk);
      float4 z1 = *(const float4*)(zs + (zr + 1) * ZSTR + kb + kk);
      float4 z2 = *(const float4*)(zs + (zr + 2) * ZSTR + kb + kk);
      float4 z3 = *(const float4*)(zs + (zr + 3) * ZSTR + kb + kk);
      float c0a[4] = {z0.x, z0.y, z0.z, z0.w};
      float c1a[4] = {z1.x, z1.y, z1.z, z1.w};
      float c2a[4] = {z2.x, z2.y, z2.z, z2.w};
      float c3a[4] = {z3.x, z3.y, z3.z, z3.w};
      #pragma unroll
      for (int s = 0; s < 4; s++) {
        u64 A0 = bc2(c0a[s]), A1 = bc2(c1a[s]), A2 = bc2(c2a[s]), A3 = bc2(c3a[s]);
        const float* wrow = Wc + (kk + s) * 512 + colg * 4;
        #pragma unroll
        for (int q = 0; q < 4; q++) {
          ulonglong2 w = *(const ulonglong2*)(wrow + q * 128);
          fma2(ag[0][q][0], A0, w.x); fma2(ag[0][q][1], A0, w.y);
          fma2(ag[1][q][0], A1, w.x); fma2(ag[1][q][1], A1, w.y);
          fma2(ag[2][q][0], A2, w.x); fma2(ag[2][q][1], A2, w.y);
          fma2(ag[3][q][0], A3, w.x); fma2(ag[3][q][1], A3, w.y);
        }
      }
    }
    __syncthreads();
  }

  // --- pointwise LSTM (q: 0=i,1=f,2=g,3=o); h_t -> zs cols 0:128 (es is dead) ---
  {
    const int rowbase = b * N_ + r0 + zr;
    #pragma unroll
    for (int j = 0; j < 4; j++) {
      float pre[4][4];
      #pragma unroll
      for (int q = 0; q < 4; q++) {
        up2(ag[j][q][0], pre[q][0], pre[q][1]);
        up2(ag[j][q][1], pre[q][2], pre[q][3]);
      }
      float* crow = g_c + (size_t)(rowbase + j) * NH_ + colg * 4;
      float4 co = *(const float4*)crow;
      float cin[4] = {co.x, co.y, co.z, co.w};
      float cn[4], hh[4];
      #pragma unroll
      for (int pp = 0; pp < 4; pp++) {
        float iv = fsgm(pre[0][pp]);
        float fv = fsgm(pre[1][pp]);
        float gv = tanhf(pre[2][pp]);
        float ov = fsgm(pre[3][pp]);
        cn[pp] = fv * cin[pp] + iv * gv;
        hh[pp] = ov * tanhf(cn[pp]);
      }
      *(float4*)crow = make_float4(cn[0], cn[1], cn[2], cn[3]);
      float4 hv = make_float4(hh[0], hh[1], hh[2], hh[3]);
      *(float4*)(hnext + (size_t)(rowbase + j) * NH_ + colg * 4) = hv;
      *(float4*)(zs + (zr + j) * ZSTR + colg * 4) = hv;
    }
  }
  __syncthreads();

  // --- out[t] = out[t-1] + h @ Wout + bout  (h in zs cols 0:128, Wout in Y) ---
  {
    int co0 = cblk * 4;
    const ulonglong2* bp = (const ulonglong2*)(p.bout + co0);
    ulonglong2 bb = bp[0];
    u64 oa00 = bb.x, oa01 = bb.y, oa10 = bb.x, oa11 = bb.y;
    #pragma unroll 4
    for (int k = 0; k < NH_; k += 4) {
      float4 a0v = *(const float4*)(zs + rA * ZSTR + k);
      float4 a1v = *(const float4*)(zs + rB * ZSTR + k);
      float a0c[4] = {a0v.x, a0v.y, a0v.z, a0v.w};
      float a1c[4] = {a1v.x, a1v.y, a1v.z, a1v.w};
      #pragma unroll
      for (int s = 0; s < 4; s++) {
        u64 A0 = bc2(a0c[s]), A1 = bc2(a1c[s]);
        ulonglong2 w = *(const ulonglong2*)(Yb + (k + s) * 64 + co0);
        fma2(oa00, A0, w.x); fma2(oa01, A0, w.y);
        fma2(oa10, A1, w.x); fma2(oa11, A1, w.y);
      }
    }
    #pragma unroll
    for (int rr = 0; rr < 2; rr++) {
      int r = (rr ? rB : rA);
      size_t gb = (size_t)(b * N_ + r0 + r) * (T_ * NIN_);
      float4 prev = *(const float4*)(p.out + gb + (size_t)(t - 1) * NIN_ + co0);
      float x0, x1, x2, x3;
      if (rr == 0) { up2(oa00, x0, x1); up2(oa01, x2, x3); }
      else         { up2(oa10, x0, x1); up2(oa11, x2, x3); }
      float4 nw = make_float4(prev.x + x0, prev.y + x1, prev.z + x2, prev.w + x3);
      *(float4*)(p.out + gb + (size_t)t * NIN_ + co0) = nw;
    }
  }
}

// ---------------- host launch ----------------
extern "C" void kernel_launch(void* const* d_in, const int* in_sizes, int n_in,
                              void* d_out, int out_size) {
  const float* X   = (const float*)d_in[0];
  const float* A   = (const float*)d_in[1];
  const float* Wse = (const float*)d_in[2];
  const float* bse = (const float*)d_in[3];
  StepP p;
  p.Wpe  = (const float*)d_in[4];  p.bpe  = (const float*)d_in[5];
  p.Wii  = (const float*)d_in[6];  p.bii  = (const float*)d_in[7];
  p.Whi  = (const float*)d_in[8];  p.bhi  = (const float*)d_in[9];
  p.Wif  = (const float*)d_in[10]; p.bif  = (const float*)d_in[11];
  p.Whf  = (const float*)d_in[12]; p.bhf  = (const float*)d_in[13];
  p.Wig  = (const float*)d_in[14]; p.big  = (const float*)d_in[15];
  p.Whg  = (const float*)d_in[16]; p.bhg  = (const float*)d_in[17];
  p.Wio  = (const float*)d_in[18]; p.bio  = (const float*)d_in[19];
  p.Who  = (const float*)d_in[20]; p.bho  = (const float*)d_in[21];
  p.Wout = (const float*)d_in[22]; p.bout = (const float*)d_in[23];
  p.out  = (float*)d_out;

  const int SMEM = SM_TOTF * 4;  // 214,016 B
  cudaFuncSetAttribute(k_step, cudaFuncAttributeMaxDynamicSharedMemorySize, SMEM);

  k_dinv<<<ROWS_, 128>>>(A);
  k_an<<<2048, 256>>>(A);
  k_fuse<<<768, 256>>>(p);
  k_init<<<2048, 256>>>(X, Wse, bse, p.out);
  for (int t = 1; t < T_; t++) {
    k_step<<<dim3(N_ / 32, B_), 256, SMEM>>>(p, t);
  }
}

// round 12
// speedup vs baseline: 3.4293x; 1.4584x over previous
#include <cuda_runtime.h>
#include <cuda_bf16.h>
#include <math.h>
#include <stdint.h>

#define B_    8
#define N_    512
#define T_    64
#define NIN_  64
#define NEMB_ 128
#define NH_   128
#define ROWS_ (B_ * N_)

typedef unsigned long long u64;
typedef unsigned int u32;

// ---------------- device scratch ----------------
__device__ float g_An[B_ * N_ * N_];
__device__ float g_dinv[ROWS_];
__device__ float g_es[ROWS_ * NEMB_];
__device__ float g_h[2][ROWS_ * NH_];
__device__ float g_c[ROWS_ * NH_];
// gate weights, bf16 hi/lo, fragment-packed: [12 chunks][hi 8192 w | lo 8192 w]
__device__ u32   g_Wzb[12 * 16384];
__device__ float g_bzp[512];         // permuted fused bias: n' = hcol*4 + q

// ---------------- packed f32x2 helpers ----------------
__device__ __forceinline__ u64 pk2(float x, float y) {
  u64 r; asm("mov.b64 %0, {%1, %2};" : "=l"(r) : "f"(x), "f"(y)); return r;
}
__device__ __forceinline__ u64 bc2(float x) { return pk2(x, x); }
__device__ __forceinline__ void up2(u64 v, float& x, float& y) {
  asm("mov.b64 {%0, %1}, %2;" : "=f"(x), "=f"(y) : "l"(v));
}
__device__ __forceinline__ void fma2(u64& d, u64 a, u64 b) {
  asm("fma.rn.f32x2 %0, %1, %2, %0;" : "+l"(d) : "l"(a), "l"(b));
}
__device__ __forceinline__ float fsgm(float x) {
  float e; asm("ex2.approx.f32 %0, %1;" : "=f"(e) : "f"(-1.4426950408889634f * x));
  float r; asm("rcp.approx.f32 %0, %1;" : "=f"(r) : "f"(1.0f + e));
  return r;
}
// cp.async
__device__ __forceinline__ uint32_t s2u(const void* p) {
  return (uint32_t)__cvta_generic_to_shared(p);
}
__device__ __forceinline__ void cp16(uint32_t d, const void* s) {
  asm volatile("cp.async.cg.shared.global [%0], [%1], 16;\n" :: "r"(d), "l"(s));
}
__device__ __forceinline__ void cpcommit() { asm volatile("cp.async.commit_group;\n"); }
template <int N> __device__ __forceinline__ void cpwait() {
  asm volatile("cp.async.wait_group %0;\n" :: "n"(N));
}

#define MMA_BF16(acc, a0, a1, a2, a3, b0, b1)                                   \
  asm volatile(                                                                 \
      "mma.sync.aligned.m16n8k16.row.col.f32.bf16.bf16.f32 "                    \
      "{%0,%1,%2,%3}, {%4,%5,%6,%7}, {%8,%9}, {%0,%1,%2,%3};"                   \
      : "+f"(acc[0]), "+f"(acc[1]), "+f"(acc[2]), "+f"(acc[3])                  \
      : "r"(a0), "r"(a1), "r"(a2), "r"(a3), "r"(b0), "r"(b1))

// ---------------- preamble kernels ----------------
__global__ void k_dinv(const float* __restrict__ A) {
  int row = blockIdx.x;
  const float* ap = A + (size_t)row * N_;
  float s = 0.0f;
  for (int m = threadIdx.x; m < N_; m += blockDim.x) s += ap[m];
  __shared__ float red[128];
  red[threadIdx.x] = s;
  __syncthreads();
  for (int off = 64; off; off >>= 1) {
    if (threadIdx.x < off) red[threadIdx.x] += red[threadIdx.x + off];
    __syncthreads();
  }
  if (threadIdx.x == 0) {
    float d = red[0];
    g_dinv[row] = (d > 0.0f) ? (1.0f / sqrtf(d)) : 0.0f;
  }
}

__global__ void k_an(const float* __restrict__ A) {
  size_t total = (size_t)B_ * N_ * N_;
  for (size_t i = blockIdx.x * (size_t)blockDim.x + threadIdx.x; i < total;
       i += (size_t)gridDim.x * blockDim.x) {
    int m = (int)(i & 511);
    size_t r = i >> 9;
    int n = (int)(r & 511);
    int b = (int)(r >> 9);
    g_An[i] = A[i] * g_dinv[b * N_ + n] * g_dinv[b * N_ + m];
  }
}

__global__ void k_init(const float* __restrict__ X, const float* __restrict__ Wse,
                       const float* __restrict__ bse, float* __restrict__ out) {
  int tid = blockIdx.x * blockDim.x + threadIdx.x;
  int row = tid >> 7;
  int c = tid & 127;
  const float* x0 = X + (size_t)row * (T_ * NIN_);
  float acc = bse[c];
  #pragma unroll 8
  for (int k = 0; k < NIN_; k++) acc += x0[k] * Wse[k * NEMB_ + c];
  g_es[(size_t)row * NEMB_ + c] = acc;
  g_h[0][tid] = 0.0f;
  g_c[tid] = 0.0f;
  if (c < NIN_) out[(size_t)row * (T_ * NIN_) + c] = x0[c];
}

struct StepP {
  const float *Wpe, *bpe, *Wii, *bii, *Whi, *bhi, *Wif, *bif, *Whf, *bhf,
              *Wig, *big, *Whg, *bhg, *Wio, *bio, *Who, *bho, *Wout, *bout;
  float* out;
};

__device__ __forceinline__ float fused_w(const StepP& p, int k, int q, int hcol) {
  const float* Wx = q == 0 ? p.Wii : q == 1 ? p.Wif : q == 2 ? p.Wig : p.Wio;
  if (k < 128) return Wx[k * 128 + hcol];
  if (k < 256) {
    float s = 0.0f;
    #pragma unroll 4
    for (int m = 0; m < 128; m++)
      s += p.Wpe[(k - 128) * 128 + m] * Wx[(128 + m) * 128 + hcol];
    return s;
  }
  const float* Wh = q == 0 ? p.Whi : q == 1 ? p.Whf : q == 2 ? p.Whg : p.Who;
  return Wh[(k - 256) * 128 + hcol];
}

__device__ __forceinline__ u32 pack_bf(float a, float b) {
  __nv_bfloat16 ha = __float2bfloat16_rn(a), hb = __float2bfloat16_rn(b);
  return (u32)__bfloat16_as_ushort(ha) | ((u32)__bfloat16_as_ushort(hb) << 16);
}

// Build packed bf16 hi/lo gate weights + permuted bias (eh fold included).
__global__ void k_fuse(StepP p) {
  int idx = blockIdx.x * blockDim.x + threadIdx.x;   // 0 .. 98303
  if (idx < 98304) {
    int np = idx & 511;             // permuted col n' = hcol*4 + q
    int kp = idx >> 9;              // 0..191 (pairs of k)
    int k0 = kp * 2;
    int hcol = np >> 2, q = np & 3;
    float v0 = fused_w(p, k0, q, hcol);
    float v1 = fused_w(p, k0 + 1, q, hcol);
    __nv_bfloat16 h0 = __float2bfloat16_rn(v0), h1 = __float2bfloat16_rn(v1);
    float l0 = v0 - __bfloat162float(h0), l1 = v1 - __bfloat162float(h1);
    // fragment-packed destination
    int kc = k0 >> 5, kt = (k0 >> 4) & 1, kr = k0 & 15;
    int j = kr >> 3, tg = (kr & 7) >> 1;
    int nt = np >> 3, g = np & 7, lane = g * 4 + tg;
    int w = kc * 16384 + ((kt * 64 + nt) * 32 + lane) * 2 + j;
    g_Wzb[w] = (u32)__bfloat16_as_ushort(h0) | ((u32)__bfloat16_as_ushort(h1) << 16);
    g_Wzb[w + 8192] = pack_bf(l0, l1);
  }
  if (idx < 512) {
    int hcol = idx >> 2, q = idx & 3;
    const float* Wx = q == 0 ? p.Wii : q == 1 ? p.Wif : q == 2 ? p.Wig : p.Wio;
    const float* bx = q == 0 ? p.bii : q == 1 ? p.bif : q == 2 ? p.big : p.bio;
    const float* bh = q == 0 ? p.bhi : q == 1 ? p.bhf : q == 2 ? p.bhg : p.bho;
    float s = bx[hcol] + bh[hcol];
    #pragma unroll 4
    for (int m = 0; m < 128; m++)
      s += p.bpe[m] * Wx[(128 + m) * 128 + hcol];
    g_bzp[idx] = s;
  }
}

// ---------------- step kernel ----------------
// smem byte offsets:
#define SMB_ZS   0        // fp32 z [32][384] = 49,152   (phase 1-2; hS/WoutS do NOT alias this)
#define SMB_ZB   49152    // zb_hi bf16 [32][392] = 25,088 ; also GEMM1 Abuf [2][32*128]f32 ; later hS [32][132]f32
#define SMB_ZBL  74240    // zb_lo bf16 [32][392] = 25,088
#define SMB_WB   99328    // 131,072: GEMM1 hbuf [2][128*128]f32 ; gate chunks [2][16384 u32] ; later WoutS
#define SM_BYTES 230400

__global__ void __launch_bounds__(256, 1) k_step(StepP p, int t) {
  extern __shared__ char smc[];
  float* zs = (float*)(smc + SMB_ZS);                 // [32][384]
  __nv_bfloat16* zbh = (__nv_bfloat16*)(smc + SMB_ZB);
  __nv_bfloat16* zbl = (__nv_bfloat16*)(smc + SMB_ZBL);
  float* hbuf = (float*)(smc + SMB_WB);               // [2][16384]
  float* Abuf = (float*)(smc + SMB_ZB);               // [2][4096]
  u32*   Wch  = (u32*)(smc + SMB_WB);                 // [2][16384]
  float* WoutS = (float*)(smc + SMB_WB);              // [128][64]
  float* hS = (float*)(smc + SMB_ZB);                 // [32][132]

  const float* hprev = g_h[(t - 1) & 1];
  float* hnext = g_h[t & 1];

  const int b = blockIdx.y;
  const int r0 = blockIdx.x * 32;
  const int tid = threadIdx.x;

  const float* esb = g_es + (size_t)(b * N_ + r0) * NEMB_;
  const float* hpb = hprev + (size_t)b * N_ * NH_;
  const float* hpr = hpb + (size_t)r0 * NH_;
  const float* Anb = g_An + (size_t)(b * N_ + r0) * N_;

  // --- stage z: es -> cols 0:128, h_prev -> cols 256:384 ---
  #pragma unroll
  for (int j = 0; j < 4; j++) {
    int idx = tid + j * 256;
    int r = idx >> 5, c4 = (idx & 31) * 4;
    cp16(s2u(zs + r * 384 + c4), esb + r * NEMB_ + c4);
    cp16(s2u(zs + r * 384 + 256 + c4), hpr + r * NH_ + c4);
  }
  cpcommit();

  // --- GEMM1: H[32x128] = An_tile @ h_prev, K=512, 4 chunks of 128 (fp32 FFMA2) ---
  const int rA = tid >> 4, rB = (tid >> 4) + 16;
  const int cblk = tid & 15;

  {
    #pragma unroll
    for (int j = 0; j < 16; j++) {
      int idx = tid + j * 256;
      int r = idx >> 5, c4 = (idx & 31) * 4;
      cp16(s2u(hbuf + r * 128 + c4), hpb + (size_t)r * NH_ + c4);
    }
    #pragma unroll
    for (int j = 0; j < 4; j++) {
      int idx = tid + j * 256;
      int r = idx >> 5, k4 = (idx & 31) * 4;
      cp16(s2u(Abuf + r * 128 + k4), Anb + (size_t)r * N_ + k4);
    }
  }
  cpcommit();

  u64 aH[2][2][2];
  #pragma unroll
  for (int i = 0; i < 2; i++)
    #pragma unroll
    for (int j = 0; j < 2; j++) { aH[i][j][0] = 0ull; aH[i][j][1] = 0ull; }

  #pragma unroll 1
  for (int ch = 0; ch < 4; ch++) {
    if (ch < 3) {
      int nb = (ch + 1) & 1;
      int k0 = (ch + 1) * 128;
      #pragma unroll
      for (int j = 0; j < 16; j++) {
        int idx = tid + j * 256;
        int r = idx >> 5, c4 = (idx & 31) * 4;
        cp16(s2u(hbuf + nb * 16384 + r * 128 + c4), hpb + (size_t)(k0 + r) * NH_ + c4);
      }
      #pragma unroll
      for (int j = 0; j < 4; j++) {
        int idx = tid + j * 256;
        int r = idx >> 5, k4 = (idx & 31) * 4;
        cp16(s2u(Abuf + nb * 4096 + r * 128 + k4), Anb + (size_t)r * N_ + k0 + k4);
      }
      cpcommit();
      cpwait<1>();
    } else {
      cpwait<0>();
    }
    __syncthreads();
    const float* hc = hbuf + (ch & 1) * 16384;
    const float* Ac = Abuf + (ch & 1) * 4096;
    #pragma unroll 4
    for (int kk = 0; kk < 128; kk += 4) {
      float4 a0v = *(const float4*)(Ac + rA * 128 + kk);
      float4 a1v = *(const float4*)(Ac + rB * 128 + kk);
      float a0c[4] = {a0v.x, a0v.y, a0v.z, a0v.w};
      float a1c[4] = {a1v.x, a1v.y, a1v.z, a1v.w};
      #pragma unroll
      for (int s = 0; s < 4; s++) {
        u64 A0 = bc2(a0c[s]), A1 = bc2(a1c[s]);
        const float* hrow = hc + (kk + s) * 128 + cblk * 4;
        ulonglong2 w0 = *(const ulonglong2*)(hrow);
        ulonglong2 w1 = *(const ulonglong2*)(hrow + 64);
        fma2(aH[0][0][0], A0, w0.x); fma2(aH[0][0][1], A0, w0.y);
        fma2(aH[0][1][0], A0, w1.x); fma2(aH[0][1][1], A0, w1.y);
        fma2(aH[1][0][0], A1, w0.x); fma2(aH[1][0][1], A1, w0.y);
        fma2(aH[1][1][0], A1, w1.x); fma2(aH[1][1][1], A1, w1.y);
      }
    }
    __syncthreads();
  }

  // store H into z cols 128:256 (fp32)
  {
    float4 v;
    up2(aH[0][0][0], v.x, v.y); up2(aH[0][0][1], v.z, v.w);
    *(float4*)(zs + rA * 384 + 128 + cblk * 4) = v;
    up2(aH[0][1][0], v.x, v.y); up2(aH[0][1][1], v.z, v.w);
    *(float4*)(zs + rA * 384 + 192 + cblk * 4) = v;
    up2(aH[1][0][0], v.x, v.y); up2(aH[1][0][1], v.z, v.w);
    *(float4*)(zs + rB * 384 + 128 + cblk * 4) = v;
    up2(aH[1][1][0], v.x, v.y); up2(aH[1][1][1], v.z, v.w);
    *(float4*)(zs + rB * 384 + 192 + cblk * 4) = v;
  }
  __syncthreads();

  // --- prefetch gate chunk 0, then convert z -> bf16 hi/lo ---
  #pragma unroll
  for (int j = 0; j < 16; j++) {
    int idx = tid + j * 256;
    cp16(s2u((char*)Wch + idx * 16), (const char*)g_Wzb + idx * 16);
  }
  cpcommit();

  #pragma unroll 1
  for (int i = 0; i < 24; i++) {
    int pr = tid + i * 256;          // pair index, 6144 pairs
    int e0 = pr * 2;
    int r = e0 / 384, c = e0 - r * 384;
    float2 f = *(const float2*)(zs + e0);
    __nv_bfloat16 h0 = __float2bfloat16_rn(f.x), h1 = __float2bfloat16_rn(f.y);
    *(u32*)(zbh + r * 392 + c) =
        (u32)__bfloat16_as_ushort(h0) | ((u32)__bfloat16_as_ushort(h1) << 16);
    *(u32*)(zbl + r * 392 + c) =
        pack_bf(f.x - __bfloat162float(h0), f.y - __bfloat162float(h1));
  }
  __syncthreads();

  // --- gate GEMM: pre[32x512'] = z @ Wz (bf16-split mma), 12 chunks of 32 k ---
  const int wrp = tid >> 5;
  const int lane = tid & 31;
  const int mt = wrp & 1;            // m-tile (16 rows)
  const int nr = wrp >> 1;           // n-range: 16 n-tiles
  const int g = lane >> 2, tg = lane & 3;

  float acc[16][4];
  #pragma unroll
  for (int n = 0; n < 16; n++) {
    int col0 = (nr * 16 + n) * 8 + 2 * tg;
    float2 bb = *(const float2*)(g_bzp + col0);
    acc[n][0] = bb.x; acc[n][1] = bb.y; acc[n][2] = bb.x; acc[n][3] = bb.y;
  }

  #pragma unroll 1
  for (int ch = 0; ch < 12; ch++) {
    if (ch < 11) {
      int nb = (ch + 1) & 1;
      const char* src = (const char*)g_Wzb + (size_t)(ch + 1) * 65536;
      #pragma unroll
      for (int j = 0; j < 16; j++) {
        int idx = tid + j * 256;
        cp16(s2u((char*)Wch + nb * 65536 + idx * 16), src + idx * 16);
      }
      cpcommit();
      cpwait<1>();
    } else {
      cpwait<0>();
    }
    __syncthreads();
    const u32* Wc = Wch + (ch & 1) * 16384;
    #pragma unroll
    for (int kt = 0; kt < 2; kt++) {
      int kb = ch * 32 + kt * 16 + 2 * tg;
      int ra = mt * 16 + g;
      u32 ah0 = *(const u32*)(zbh + ra * 392 + kb);
      u32 ah1 = *(const u32*)(zbh + (ra + 8) * 392 + kb);
      u32 ah2 = *(const u32*)(zbh + ra * 392 + kb + 8);
      u32 ah3 = *(const u32*)(zbh + (ra + 8) * 392 + kb + 8);
      u32 al0 = *(const u32*)(zbl + ra * 392 + kb);
      u32 al1 = *(const u32*)(zbl + (ra + 8) * 392 + kb);
      u32 al2 = *(const u32*)(zbl + ra * 392 + kb + 8);
      u32 al3 = *(const u32*)(zbl + (ra + 8) * 392 + kb + 8);
      const u32* base = Wc + (kt * 64 + nr * 16) * 64 + lane * 2;
      #pragma unroll
      for (int n = 0; n < 16; n++) {
        uint2 bh = *(const uint2*)(base + n * 64);
        uint2 bl = *(const uint2*)(base + 8192 + n * 64);
        MMA_BF16(acc[n], ah0, ah1, ah2, ah3, bh.x, bh.y);
        MMA_BF16(acc[n], ah0, ah1, ah2, ah3, bl.x, bl.y);
        MMA_BF16(acc[n], al0, al1, al2, al3, bh.x, bh.y);
      }
    }
    __syncthreads();
  }

  // --- prefetch Wout (into Wch[0] region) ---
  #pragma unroll
  for (int j = 0; j < 8; j++) {
    int idx = tid + j * 256;
    int r = idx >> 4, c4 = (idx & 15) * 4;
    cp16(s2u(WoutS + r * 64 + c4), p.Wout + r * 64 + c4);
  }
  cpcommit();

  // --- pointwise LSTM (writes c to global, h_t to hS over dead zb region) ---
  {
    int odd = tg & 1;
    #pragma unroll
    for (int n = 0; n < 16; n++) {
      float c0 = acc[n][0], c1 = acc[n][1], c2 = acc[n][2], c3 = acc[n][3];
      float sa = odd ? c0 : c2;
      float sb = odd ? c1 : c3;
      float ra = __shfl_xor_sync(0xffffffffu, sa, 1);
      float rb = __shfl_xor_sync(0xffffffffu, sb, 1);
      float pi = odd ? ra : c0;
      float pf = odd ? rb : c1;
      float pg = odd ? c2 : ra;
      float po = odd ? c3 : rb;
      int row = mt * 16 + g + 8 * odd;
      int hcol = nr * 32 + n * 2 + (tg >> 1);
      int gr = b * N_ + r0 + row;
      float cold = g_c[(size_t)gr * NH_ + hcol];
      float iv = fsgm(pi), fv = fsgm(pf);
      float gv = tanhf(pg), ov = fsgm(po);
      float cn = fv * cold + iv * gv;
      float hv = ov * tanhf(cn);
      g_c[(size_t)gr * NH_ + hcol] = cn;
      hS[row * 132 + hcol] = hv;
    }
  }
  cpwait<0>();
  __syncthreads();

  // --- copy h_t to global (coalesced) ---
  #pragma unroll
  for (int j = 0; j < 4; j++) {
    int idx = tid + j * 256;            // 1024 float4
    int row = idx >> 5, c4 = (idx & 31) * 4;
    float4 v = *(const float4*)(hS + row * 132 + c4);
    *(float4*)(hnext + (size_t)(b * N_ + r0 + row) * NH_ + c4) = v;
  }

  // --- out[t] = out[t-1] + h @ Wout + bout (fp32 FFMA2) ---
  {
    int co0 = cblk * 4;
    const ulonglong2* bp = (const ulonglong2*)(p.bout + co0);
    ulonglong2 bb = bp[0];
    u64 oa00 = bb.x, oa01 = bb.y, oa10 = bb.x, oa11 = bb.y;
    #pragma unroll 4
    for (int k = 0; k < NH_; k += 4) {
      float4 a0v = *(const float4*)(hS + rA * 132 + k);
      float4 a1v = *(const float4*)(hS + rB * 132 + k);
      float a0c[4] = {a0v.x, a0v.y, a0v.z, a0v.w};
      float a1c[4] = {a1v.x, a1v.y, a1v.z, a1v.w};
      #pragma unroll
      for (int s = 0; s < 4; s++) {
        u64 A0 = bc2(a0c[s]), A1 = bc2(a1c[s]);
        ulonglong2 w = *(const ulonglong2*)(WoutS + (k + s) * 64 + co0);
        fma2(oa00, A0, w.x); fma2(oa01, A0, w.y);
        fma2(oa10, A1, w.x); fma2(oa11, A1, w.y);
      }
    }
    #pragma unroll
    for (int rr = 0; rr < 2; rr++) {
      int r = (rr ? rB : rA);
      size_t gb = (size_t)(b * N_ + r0 + r) * (T_ * NIN_);
      float4 prev = *(const float4*)(p.out + gb + (size_t)(t - 1) * NIN_ + co0);
      float x0, x1, x2, x3;
      if (rr == 0) { up2(oa00, x0, x1); up2(oa01, x2, x3); }
      else         { up2(oa10, x0, x1); up2(oa11, x2, x3); }
      float4 nw = make_float4(prev.x + x0, prev.y + x1, prev.z + x2, prev.w + x3);
      *(float4*)(p.out + gb + (size_t)t * NIN_ + co0) = nw;
    }
  }
}

// ---------------- host launch ----------------
extern "C" void kernel_launch(void* const* d_in, const int* in_sizes, int n_in,
                              void* d_out, int out_size) {
  const float* X   = (const float*)d_in[0];
  const float* A   = (const float*)d_in[1];
  const float* Wse = (const float*)d_in[2];
  const float* bse = (const float*)d_in[3];
  StepP p;
  p.Wpe  = (const float*)d_in[4];  p.bpe  = (const float*)d_in[5];
  p.Wii  = (const float*)d_in[6];  p.bii  = (const float*)d_in[7];
  p.Whi  = (const float*)d_in[8];  p.bhi  = (const float*)d_in[9];
  p.Wif  = (const float*)d_in[10]; p.bif  = (const float*)d_in[11];
  p.Whf  = (const float*)d_in[12]; p.bhf  = (const float*)d_in[13];
  p.Wig  = (const float*)d_in[14]; p.big  = (const float*)d_in[15];
  p.Whg  = (const float*)d_in[16]; p.bhg  = (const float*)d_in[17];
  p.Wio  = (const float*)d_in[18]; p.bio  = (const float*)d_in[19];
  p.Who  = (const float*)d_in[20]; p.bho  = (const float*)d_in[21];
  p.Wout = (const float*)d_in[22]; p.bout = (const float*)d_in[23];
  p.out  = (float*)d_out;

  cudaFuncSetAttribute(k_step, cudaFuncAttributeMaxDynamicSharedMemorySize, SM_BYTES);

  k_dinv<<<ROWS_, 128>>>(A);
  k_an<<<2048, 256>>>(A);
  k_fuse<<<384, 256>>>(p);
  k_init<<<2048, 256>>>(X, Wse, bse, p.out);
  for (int t = 1; t < T_; t++) {
    k_step<<<dim3(N_ / 32, B_), 256, SM_BYTES>>>(p, t);
  }
}

// round 15
// speedup vs baseline: 4.8246x; 1.4069x over previous
#include <cuda_runtime.h>
#include <cuda_bf16.h>
#include <math.h>
#include <stdint.h>

#define B_    8
#define N_    512
#define T_    64
#define NIN_  64
#define NEMB_ 128
#define NH_   128
#define ROWS_ (B_ * N_)

typedef unsigned long long u64;
typedef unsigned int u32;

// ---------------- device scratch ----------------
__device__ float g_dinv[ROWS_];
__device__ float g_c[ROWS_ * NH_];
// es bf16 hi/lo, row-major [4096][128]
__device__ u32 g_esb_hi32[ROWS_ * 64];
__device__ u32 g_esb_lo32[ROWS_ * 64];
// h bf16 hi/lo row-major [4096][128], double-buffered
__device__ u32 g_hb_hi32[2][ROWS_ * 64];
__device__ u32 g_hb_lo32[2][ROWS_ * 64];
// h^T bf16 hi/lo [b][hcol 128][node 512], double-buffered
__device__ u32 g_hbT_hi32[2][B_ * NH_ * 256];
__device__ u32 g_hbT_lo32[2][B_ * NH_ * 256];
// An packed mma B-fragments: [b][tile16][kchunk4][hi 2048 u32 | lo 2048 u32]
__device__ u32 g_Anb[B_ * 16 * 4 * 4096];
// gate weights bf16 hi/lo fragment-packed: [12 chunks][hi 8192 | lo 8192]
__device__ u32 g_Wzb[12 * 16384];
__device__ float g_bzp[512];         // permuted fused bias: n' = hcol*4 + q

// ---------------- helpers ----------------
__device__ __forceinline__ u64 pk2(float x, float y) {
  u64 r; asm("mov.b64 %0, {%1, %2};" : "=l"(r) : "f"(x), "f"(y)); return r;
}
__device__ __forceinline__ u64 bc2(float x) { return pk2(x, x); }
__device__ __forceinline__ void up2(u64 v, float& x, float& y) {
  asm("mov.b64 {%0, %1}, %2;" : "=f"(x), "=f"(y) : "l"(v));
}
__device__ __forceinline__ void fma2(u64& d, u64 a, u64 b) {
  asm("fma.rn.f32x2 %0, %1, %2, %0;" : "+l"(d) : "l"(a), "l"(b));
}
__device__ __forceinline__ float fsgm(float x) {
  float e; asm("ex2.approx.f32 %0, %1;" : "=f"(e) : "f"(-1.4426950408889634f * x));
  float r; asm("rcp.approx.f32 %0, %1;" : "=f"(r) : "f"(1.0f + e));
  return r;
}
__device__ __forceinline__ uint32_t s2u(const void* p) {
  return (uint32_t)__cvta_generic_to_shared(p);
}
__device__ __forceinline__ void cp16(uint32_t d, const void* s) {
  asm volatile("cp.async.cg.shared.global [%0], [%1], 16;\n" :: "r"(d), "l"(s));
}
__device__ __forceinline__ void cpcommit() { asm volatile("cp.async.commit_group;\n"); }
template <int N> __device__ __forceinline__ void cpwait() {
  asm volatile("cp.async.wait_group %0;\n" :: "n"(N));
}

#define MMA_BF16(acc, a0, a1, a2, a3, b0, b1)                                   \
  asm volatile(                                                                 \
      "mma.sync.aligned.m16n8k16.row.col.f32.bf16.bf16.f32 "                    \
      "{%0,%1,%2,%3}, {%4,%5,%6,%7}, {%8,%9}, {%0,%1,%2,%3};"                   \
      : "+f"(acc[0]), "+f"(acc[1]), "+f"(acc[2]), "+f"(acc[3])                  \
      : "r"(a0), "r"(a1), "r"(a2), "r"(a3), "r"(b0), "r"(b1))

// ---------------- preamble kernels ----------------
__global__ void k_dinv(const float* __restrict__ A) {
  int row = blockIdx.x;
  const float* ap = A + (size_t)row * N_;
  float s = 0.0f;
  for (int m = threadIdx.x; m < N_; m += blockDim.x) s += ap[m];
  __shared__ float red[128];
  red[threadIdx.x] = s;
  __syncthreads();
  for (int off = 64; off; off >>= 1) {
    if (threadIdx.x < off) red[threadIdx.x] += red[threadIdx.x + off];
    __syncthreads();
  }
  if (threadIdx.x == 0) {
    float d = red[0];
    g_dinv[row] = (d > 0.0f) ? (1.0f / sqrtf(d)) : 0.0f;
  }
}

// Normalize An and pack straight into mma B fragments (bf16 hi/lo).
__global__ void k_an(const float* __restrict__ A) {
  #pragma unroll 1
  for (int it = 0; it < 4; it++) {
    int i = blockIdx.x * blockDim.x + threadIdx.x + it * 524288;
    int m = i & 511;
    int r = (i >> 9) & 511;
    int b = i >> 18;
    float v = A[i] * g_dinv[b * N_ + r] * g_dinv[b * N_ + m];
    __nv_bfloat16 hi = __float2bfloat16_rn(v);
    __nv_bfloat16 lo = __float2bfloat16_rn(v - __bfloat162float(hi));
    int tile = r >> 5, n = r & 31;
    int chunk = m >> 7, kp = m & 127;
    int ks = kp >> 4;
    int j = (kp >> 3) & 1, tg = (kp & 7) >> 1, par = m & 1;
    int nt = n >> 3, g = n & 7, lane = g * 4 + tg;
    int u = ((b * 16 + tile) * 4 + chunk) * 4096 + (ks * 4 + nt) * 64 + lane * 2 + j;
    ((__nv_bfloat16*)g_Anb)[u * 2 + par] = hi;
    ((__nv_bfloat16*)g_Anb)[(u + 2048) * 2 + par] = lo;
  }
}

__global__ void k_init(const float* __restrict__ X, const float* __restrict__ Wse,
                       const float* __restrict__ bse, float* __restrict__ out) {
  int tid = blockIdx.x * blockDim.x + threadIdx.x;
  int row = tid >> 7;
  int c = tid & 127;
  const float* x0 = X + (size_t)row * (T_ * NIN_);
  float acc = bse[c];
  #pragma unroll 8
  for (int k = 0; k < NIN_; k++) acc += x0[k] * Wse[k * NEMB_ + c];
  __nv_bfloat16 hi = __float2bfloat16_rn(acc);
  __nv_bfloat16 lo = __float2bfloat16_rn(acc - __bfloat162float(hi));
  ((__nv_bfloat16*)g_esb_hi32)[tid] = hi;
  ((__nv_bfloat16*)g_esb_lo32)[tid] = lo;
  g_c[tid] = 0.0f;
  __nv_bfloat16 z = __float2bfloat16_rn(0.0f);
  ((__nv_bfloat16*)g_hb_hi32[0])[tid] = z;
  ((__nv_bfloat16*)g_hb_lo32[0])[tid] = z;
  int b = row >> 9, node = row & 511;
  ((__nv_bfloat16*)g_hbT_hi32[0])[((size_t)(b * 128 + c)) * 512 + node] = z;
  ((__nv_bfloat16*)g_hbT_lo32[0])[((size_t)(b * 128 + c)) * 512 + node] = z;
  if (c < NIN_) out[(size_t)row * (T_ * NIN_) + c] = x0[c];
}

struct StepP {
  const float *Wpe, *bpe, *Wii, *bii, *Whi, *bhi, *Wif, *bif, *Whf, *bhf,
              *Wig, *big, *Whg, *bhg, *Wio, *bio, *Who, *bho, *Wout, *bout;
  float* out;
};

__device__ __forceinline__ float fused_w(const StepP& p, int k, int q, int hcol) {
  const float* Wx = q == 0 ? p.Wii : q == 1 ? p.Wif : q == 2 ? p.Wig : p.Wio;
  if (k < 128) return Wx[k * 128 + hcol];
  if (k < 256) {
    float s = 0.0f;
    #pragma unroll 4
    for (int m = 0; m < 128; m++)
      s += p.Wpe[(k - 128) * 128 + m] * Wx[(128 + m) * 128 + hcol];
    return s;
  }
  const float* Wh = q == 0 ? p.Whi : q == 1 ? p.Whf : q == 2 ? p.Whg : p.Who;
  return Wh[(k - 256) * 128 + hcol];
}

__device__ __forceinline__ u32 pack_bf(float a, float b) {
  __nv_bfloat16 ha = __float2bfloat16_rn(a), hb = __float2bfloat16_rn(b);
  return (u32)__bfloat16_as_ushort(ha) | ((u32)__bfloat16_as_ushort(hb) << 16);
}

__global__ void k_fuse(StepP p) {
  int idx = blockIdx.x * blockDim.x + threadIdx.x;
  if (idx < 98304) {
    int np = idx & 511;
    int kp = idx >> 9;
    int k0 = kp * 2;
    int hcol = np >> 2, q = np & 3;
    float v0 = fused_w(p, k0, q, hcol);
    float v1 = fused_w(p, k0 + 1, q, hcol);
    __nv_bfloat16 h0 = __float2bfloat16_rn(v0), h1 = __float2bfloat16_rn(v1);
    float l0 = v0 - __bfloat162float(h0), l1 = v1 - __bfloat162float(h1);
    int kc = k0 >> 5, kt = (k0 >> 4) & 1, kr = k0 & 15;
    int j = kr >> 3, tg = (kr & 7) >> 1;
    int nt = np >> 3, g = np & 7, lane = g * 4 + tg;
    int w = kc * 16384 + ((kt * 64 + nt) * 32 + lane) * 2 + j;
    g_Wzb[w] = (u32)__bfloat16_as_ushort(h0) | ((u32)__bfloat16_as_ushort(h1) << 16);
    g_Wzb[w + 8192] = pack_bf(l0, l1);
  }
  if (idx < 512) {
    int hcol = idx >> 2, q = idx & 3;
    const float* Wx = q == 0 ? p.Wii : q == 1 ? p.Wif : q == 2 ? p.Wig : p.Wio;
    const float* bx = q == 0 ? p.bii : q == 1 ? p.bif : q == 2 ? p.big : p.bio;
    const float* bh = q == 0 ? p.bhi : q == 1 ? p.bhf : q == 2 ? p.bhg : p.bho;
    float s = bx[hcol] + bh[hcol];
    #pragma unroll 4
    for (int m = 0; m < 128; m++)
      s += p.bpe[m] * Wx[(128 + m) * 128 + hcol];
    g_bzp[idx] = s;
  }
}

// ---------------- step kernel ----------------
#define SMB_ZBH  0
#define SMB_ZBL  25088
#define SMB_BUF  50176
#define SM_BYTES 222208

// Stage one GEMM1 chunk (h^T hi/lo slice + An fragment block) into buffer nb.
__device__ __forceinline__ void stage_g1(
    char* smc, int tid, int b, const char* hbT_h, const char* hbT_l,
    const char* anb, int chunk, int nb) {
  char* base = smc + SMB_BUF + nb * 86016;
  int k0 = chunk * 128;
  #pragma unroll
  for (int j = 0; j < 8; j++) {
    int idx = tid + j * 256;
    int row = idx >> 4, c16 = idx & 15;
    long so = (long)(b * 128 + row) * 1024 + (k0 + c16 * 8) * 2;
    cp16(s2u(base + row * 272 + c16 * 16), hbT_h + so);
    cp16(s2u(base + 34816 + row * 272 + c16 * 16), hbT_l + so);
  }
  #pragma unroll
  for (int j = 0; j < 4; j++) {
    int idx = tid + j * 256;
    cp16(s2u(base + 69632 + idx * 16), anb + (size_t)chunk * 16384 + idx * 16);
  }
}

__global__ void __launch_bounds__(256, 1) k_step(StepP p, int t) {
  extern __shared__ char smc[];
  __nv_bfloat16* zbh = (__nv_bfloat16*)(smc + SMB_ZBH);
  __nv_bfloat16* zbl = (__nv_bfloat16*)(smc + SMB_ZBL);
  float* hS = (float*)(smc + SMB_ZBH);
  u32*   Wch = (u32*)(smc + SMB_BUF);
  float* WoutS = (float*)(smc + SMB_BUF + 131072);

  const int ph = (t - 1) & 1, pn = t & 1;
  const int b = blockIdx.y;
  const int r0 = blockIdx.x * 32;
  const int tid = threadIdx.x;
  const int wrp = tid >> 5, lane = tid & 31;
  const int g = lane >> 2, tg = lane & 3;
  const int baserow = b * N_ + r0;

  // --- stage zb: es (cols 0:128) + h_prev (cols 256:384), hi/lo ---
  {
    const char* eh = (const char*)g_esb_hi32;
    const char* el = (const char*)g_esb_lo32;
    const char* hh = (const char*)g_hb_hi32[ph];
    const char* hl = (const char*)g_hb_lo32[ph];
    #pragma unroll
    for (int j = 0; j < 8; j++) {
      int idx = tid + j * 256;
      int q = idx & 511;
      int r = q >> 4, c16 = q & 15;
      long so = (long)(baserow + r) * 256 + c16 * 16;
      if (j < 2)      cp16(s2u((char*)zbh + r * 784 + c16 * 16), eh + so);
      else if (j < 4) cp16(s2u((char*)zbl + r * 784 + c16 * 16), el + so);
      else if (j < 6) cp16(s2u((char*)zbh + r * 784 + 512 + c16 * 16), hh + so);
      else            cp16(s2u((char*)zbl + r * 784 + 512 + c16 * 16), hl + so);
    }
  }
  cpcommit();

  // --- GEMM1 (mma): D^T[128 hcol x 32 node] = h^T @ An^T, K=512, 4 chunks ---
  const char* hbT_h = (const char*)g_hbT_hi32[ph];
  const char* hbT_l = (const char*)g_hbT_lo32[ph];
  const char* anb = (const char*)(g_Anb + ((b * 16 + (r0 >> 5)) * 4) * 4096);

  stage_g1(smc, tid, b, hbT_h, hbT_l, anb, 0, 0);
  cpcommit();

  float aG[4][4];
  #pragma unroll
  for (int n = 0; n < 4; n++)
    #pragma unroll
    for (int j = 0; j < 4; j++) aG[n][j] = 0.0f;

  const int arow = wrp * 16 + g;

  #pragma unroll 1
  for (int ch = 0; ch < 4; ch++) {
    if (ch < 3) {
      stage_g1(smc, tid, b, hbT_h, hbT_l, anb, ch + 1, (ch + 1) & 1);
      cpcommit();
      cpwait<1>();
    } else {
      cpwait<0>();
    }
    __syncthreads();
    const char* base = smc + SMB_BUF + (ch & 1) * 86016;
    const __nv_bfloat16* Ah = (const __nv_bfloat16*)base;
    const __nv_bfloat16* Al = (const __nv_bfloat16*)(base + 34816);
    const u32* Bf = (const u32*)(base + 69632);
    #pragma unroll 2
    for (int ks = 0; ks < 8; ks++) {
      int kk = ks * 16 + tg * 2;
      u32 ah0 = *(const u32*)(Ah + arow * 136 + kk);
      u32 ah1 = *(const u32*)(Ah + (arow + 8) * 136 + kk);
      u32 ah2 = *(const u32*)(Ah + arow * 136 + kk + 8);
      u32 ah3 = *(const u32*)(Ah + (arow + 8) * 136 + kk + 8);
      u32 al0 = *(const u32*)(Al + arow * 136 + kk);
      u32 al1 = *(const u32*)(Al + (arow + 8) * 136 + kk);
      u32 al2 = *(const u32*)(Al + arow * 136 + kk + 8);
      u32 al3 = *(const u32*)(Al + (arow + 8) * 136 + kk + 8);
      #pragma unroll
      for (int nt = 0; nt < 4; nt++) {
        const u32* bp = Bf + (ks * 4 + nt) * 64 + lane * 2;
        uint2 bh = *(const uint2*)bp;
        uint2 bl = *(const uint2*)(bp + 2048);
        MMA_BF16(aG[nt], ah0, ah1, ah2, ah3, bh.x, bh.y);
        MMA_BF16(aG[nt], ah0, ah1, ah2, ah3, bl.x, bl.y);
        MMA_BF16(aG[nt], al0, al1, al2, al3, bh.x, bh.y);
      }
    }
    __syncthreads();
  }

  // write H (split hi/lo) into zb cols 128:256
  #pragma unroll
  for (int nt = 0; nt < 4; nt++) {
    #pragma unroll
    for (int j = 0; j < 4; j++) {
      float v = aG[nt][j];
      int hcol = wrp * 16 + g + 8 * (j >> 1);
      int nrow = nt * 8 + tg * 2 + (j & 1);
      __nv_bfloat16 hi = __float2bfloat16_rn(v);
      __nv_bfloat16 lo = __float2bfloat16_rn(v - __bfloat162float(hi));
      zbh[nrow * 392 + 128 + hcol] = hi;
      zbl[nrow * 392 + 128 + hcol] = lo;
    }
  }

  // prefetch gate chunk 0 + Wout (GEMM1 buffers are dead)
  #pragma unroll
  for (int j = 0; j < 16; j++) {
    int idx = tid + j * 256;
    cp16(s2u((char*)Wch + idx * 16), (const char*)g_Wzb + idx * 16);
  }
  #pragma unroll
  for (int j = 0; j < 8; j++) {
    int idx = tid + j * 256;
    int r = idx >> 4, c4 = (idx & 15) * 4;
    cp16(s2u(WoutS + r * 64 + c4), p.Wout + r * 64 + c4);
  }
  cpcommit();

  // --- gate GEMM: pre[32x512'] = z @ Wz (bf16-split), 12 chunks of 32 k ---
  const int mt = wrp & 1;
  const int nr = wrp >> 1;

  float acc[16][4];
  #pragma unroll
  for (int n = 0; n < 16; n++) {
    int col0 = (nr * 16 + n) * 8 + 2 * tg;
    float2 bb = *(const float2*)(g_bzp + col0);
    acc[n][0] = bb.x; acc[n][1] = bb.y; acc[n][2] = bb.x; acc[n][3] = bb.y;
  }

  #pragma unroll 1
  for (int ch = 0; ch < 12; ch++) {
    if (ch < 11) {
      int nb = (ch + 1) & 1;
      const char* src = (const char*)g_Wzb + (size_t)(ch + 1) * 65536;
      #pragma unroll
      for (int j = 0; j < 16; j++) {
        int idx = tid + j * 256;
        cp16(s2u((char*)Wch + nb * 65536 + idx * 16), src + idx * 16);
      }
      cpcommit();
      cpwait<1>();
    } else {
      cpwait<0>();
    }
    __syncthreads();
    const u32* Wc = Wch + (ch & 1) * 16384;
    #pragma unroll
    for (int kt = 0; kt < 2; kt++) {
      int kb = ch * 32 + kt * 16 + 2 * tg;
      int ra = mt * 16 + g;
      u32 ah0 = *(const u32*)(zbh + ra * 392 + kb);
      u32 ah1 = *(const u32*)(zbh + (ra + 8) * 392 + kb);
      u32 ah2 = *(const u32*)(zbh + ra * 392 + kb + 8);
      u32 ah3 = *(const u32*)(zbh + (ra + 8) * 392 + kb + 8);
      u32 al0 = *(const u32*)(zbl + ra * 392 + kb);
      u32 al1 = *(const u32*)(zbl + (ra + 8) * 392 + kb);
      u32 al2 = *(const u32*)(zbl + ra * 392 + kb + 8);
      u32 al3 = *(const u32*)(zbl + (ra + 8) * 392 + kb + 8);
      const u32* base = Wc + (kt * 64 + nr * 16) * 64 + lane * 2;
      #pragma unroll
      for (int n = 0; n < 16; n++) {
        uint2 bh = *(const uint2*)(base + n * 64);
        uint2 bl = *(const uint2*)(base + 8192 + n * 64);
        MMA_BF16(acc[n], ah0, ah1, ah2, ah3, bh.x, bh.y);
        MMA_BF16(acc[n], ah0, ah1, ah2, ah3, bl.x, bl.y);
        MMA_BF16(acc[n], al0, al1, al2, al3, bh.x, bh.y);
      }
    }
    __syncthreads();
  }

  // --- pointwise LSTM; h_t -> hS (aliases zb region, safe after final sync) ---
  {
    int odd = tg & 1;
    #pragma unroll
    for (int n = 0; n < 16; n++) {
      float c0 = acc[n][0], c1 = acc[n][1], c2 = acc[n][2], c3 = acc[n][3];
      float sa = odd ? c0 : c2;
      float sb = odd ? c1 : c3;
      float ra = __shfl_xor_sync(0xffffffffu, sa, 1);
      float rb = __shfl_xor_sync(0xffffffffu, sb, 1);
      float pi = odd ? ra : c0;
      float pf = odd ? rb : c1;
      float pg = odd ? c2 : ra;
      float po = odd ? c3 : rb;
      int row = mt * 16 + g + 8 * odd;
      int hcol = nr * 32 + n * 2 + (tg >> 1);
      int gr = baserow + row;
      float cold = g_c[(size_t)gr * NH_ + hcol];
      float iv = fsgm(pi), fv = fsgm(pf);
      float gv = tanhf(pg), ov = fsgm(po);
      float cn = fv * cold + iv * gv;
      float hv = ov * tanhf(cn);
      g_c[(size_t)gr * NH_ + hcol] = cn;
      hS[row * 132 + hcol] = hv;
    }
  }
  __syncthreads();

  // --- write h_t to global in bf16 hi/lo, row-major + transposed ---
  {
    u32* hbh = (u32*)g_hb_hi32[pn];
    u32* hbl = (u32*)g_hb_lo32[pn];
    #pragma unroll
    for (int j = 0; j < 8; j++) {
      int idx = tid + j * 256;
      int row = idx >> 6, cp_ = idx & 63;
      float f0 = hS[row * 132 + cp_ * 2];
      float f1 = hS[row * 132 + cp_ * 2 + 1];
      __nv_bfloat16 h0 = __float2bfloat16_rn(f0), h1 = __float2bfloat16_rn(f1);
      hbh[(size_t)(baserow + row) * 64 + cp_] =
          (u32)__bfloat16_as_ushort(h0) | ((u32)__bfloat16_as_ushort(h1) << 16);
      hbl[(size_t)(baserow + row) * 64 + cp_] =
          pack_bf(f0 - __bfloat162float(h0), f1 - __bfloat162float(h1));
    }
    u32* hTh = (u32*)g_hbT_hi32[pn];
    u32* hTl = (u32*)g_hbT_lo32[pn];
    #pragma unroll
    for (int j = 0; j < 8; j++) {
      int idx = tid + j * 256;
      int hcol = idx >> 4, jp = idx & 15;
      float f0 = hS[(2 * jp) * 132 + hcol];
      float f1 = hS[(2 * jp + 1) * 132 + hcol];
      __nv_bfloat16 h0 = __float2bfloat16_rn(f0), h1 = __float2bfloat16_rn(f1);
      size_t o = (size_t)(b * 128 + hcol) * 256 + (r0 >> 1) + jp;
      hTh[o] = (u32)__bfloat16_as_ushort(h0) | ((u32)__bfloat16_as_ushort(h1) << 16);
      hTl[o] = pack_bf(f0 - __bfloat162float(h0), f1 - __bfloat162float(h1));
    }
  }

  // --- out[t] = out[t-1] + h @ Wout + bout (fp32 FFMA2, small) ---
  {
    const int rA = tid >> 4, rB = rA + 16;
    const int co0 = (tid & 15) * 4;
    const ulonglong2* bp = (const ulonglong2*)(p.bout + co0);
    ulonglong2 bb = bp[0];
    u64 oa00 = bb.x, oa01 = bb.y, oa10 = bb.x, oa11 = bb.y;
    #pragma unroll 4
    for (int k = 0; k < NH_; k += 4) {
      float4 a0v = *(const float4*)(hS + rA * 132 + k);
      float4 a1v = *(const float4*)(hS + rB * 132 + k);
      float a0c[4] = {a0v.x, a0v.y, a0v.z, a0v.w};
      float a1c[4] = {a1v.x, a1v.y, a1v.z, a1v.w};
      #pragma unroll
      for (int s = 0; s < 4; s++) {
        u64 A0 = bc2(a0c[s]), A1 = bc2(a1c[s]);
        ulonglong2 w = *(const ulonglong2*)(WoutS + (k + s) * 64 + co0);
        fma2(oa00, A0, w.x); fma2(oa01, A0, w.y);
        fma2(oa10, A1, w.x); fma2(oa11, A1, w.y);
      }
    }
    #pragma unroll
    for (int rr = 0; rr < 2; rr++) {
      int r = (rr ? rB : rA);
      size_t gb = (size_t)(baserow + r) * (T_ * NIN_);
      float4 prev = *(const float4*)(p.out + gb + (size_t)(t - 1) * NIN_ + co0);
      float x0, x1, x2, x3;
      if (rr == 0) { up2(oa00, x0, x1); up2(oa01, x2, x3); }
      else         { up2(oa10, x0, x1); up2(oa11, x2, x3); }
      float4 nw = make_float4(prev.x + x0, prev.y + x1, prev.z + x2, prev.w + x3);
      *(float4*)(p.out + gb + (size_t)t * NIN_ + co0) = nw;
    }
  }
}

// ---------------- host launch ----------------
extern "C" void kernel_launch(void* const* d_in, const int* in_sizes, int n_in,
                              void* d_out, int out_size) {
  const float* X   = (const float*)d_in[0];
  const float* A   = (const float*)d_in[1];
  const float* Wse = (const float*)d_in[2];
  const float* bse = (const float*)d_in[3];
  StepP p;
  p.Wpe  = (const float*)d_in[4];  p.bpe  = (const float*)d_in[5];
  p.Wii  = (const float*)d_in[6];  p.bii  = (const float*)d_in[7];
  p.Whi  = (const float*)d_in[8];  p.bhi  = (const float*)d_in[9];
  p.Wif  = (const float*)d_in[10]; p.bif  = (const float*)d_in[11];
  p.Whf  = (const float*)d_in[12]; p.bhf  = (const float*)d_in[13];
  p.Wig  = (const float*)d_in[14]; p.big  = (const float*)d_in[15];
  p.Whg  = (const float*)d_in[16]; p.bhg  = (const float*)d_in[17];
  p.Wio  = (const float*)d_in[18]; p.bio  = (const float*)d_in[19];
  p.Who  = (const float*)d_in[20]; p.bho  = (const float*)d_in[21];
  p.Wout = (const float*)d_in[22]; p.bout = (const float*)d_in[23];
  p.out  = (float*)d_out;

  cudaFuncSetAttribute(k_step, cudaFuncAttributeMaxDynamicSharedMemorySize, SM_BYTES);

  k_dinv<<<ROWS_, 128>>>(A);
  k_an<<<2048, 256>>>(A);
  k_fuse<<<384, 256>>>(p);
  k_init<<<2048, 256>>>(X, Wse, bse, p.out);
  for (int t = 1; t < T_; t++) {
    k_step<<<dim3(N_ / 32, B_), 256, SM_BYTES>>>(p, t);
  }
}

// round 16
// speedup vs baseline: 5.2027x; 1.0784x over previous
#include <cuda_runtime.h>
#include <cuda_bf16.h>
#include <math.h>
#include <stdint.h>

#define B_    8
#define N_    512
#define T_    64
#define NIN_  64
#define NEMB_ 128
#define NH_   128
#define ROWS_ (B_ * N_)

typedef unsigned long long u64;
typedef unsigned int u32;

// ---------------- device scratch ----------------
__device__ float g_dinv[ROWS_];
__device__ float g_c[ROWS_ * NH_];
__device__ float g_es[ROWS_ * NEMB_];          // fp32 es (preamble only)
// h bf16 hi/lo row-major [4096][128], double-buffered
__device__ u32 g_hb_hi32[2][ROWS_ * 64];
__device__ u32 g_hb_lo32[2][ROWS_ * 64];
// h^T bf16 hi/lo [b][hcol 128][node 512], double-buffered
__device__ u32 g_hbT_hi32[2][B_ * NH_ * 256];
__device__ u32 g_hbT_lo32[2][B_ * NH_ * 256];
// An packed mma B-fragments: [b][tile16][kchunk4][hi 2048 u32 | lo 2048 u32]
__device__ u32 g_Anb[B_ * 16 * 4 * 4096];
// gate weights (k=256: H|h rows only) bf16 hi/lo fragment-packed: [8 chunks][hi 8192 | lo 8192]
__device__ u32 g_Wzb[8 * 16384];
__device__ float g_bzp[512];                   // permuted fused bias (feeds k_pre_es only)
// precomputed es gate contribution, accumulator-fragment layout:
// [b][tile16][wrp8][n16][lane32] float4
__device__ float4 g_preES[B_ * 16 * 8 * 16 * 32];

// ---------------- helpers ----------------
__device__ __forceinline__ u64 pk2(float x, float y) {
  u64 r; asm("mov.b64 %0, {%1, %2};" : "=l"(r) : "f"(x), "f"(y)); return r;
}
__device__ __forceinline__ u64 bc2(float x) { return pk2(x, x); }
__device__ __forceinline__ void up2(u64 v, float& x, float& y) {
  asm("mov.b64 {%0, %1}, %2;" : "=f"(x), "=f"(y) : "l"(v));
}
__device__ __forceinline__ void fma2(u64& d, u64 a, u64 b) {
  asm("fma.rn.f32x2 %0, %1, %2, %0;" : "+l"(d) : "l"(a), "l"(b));
}
__device__ __forceinline__ float fsgm(float x) {
  float e; asm("ex2.approx.f32 %0, %1;" : "=f"(e) : "f"(-1.4426950408889634f * x));
  float r; asm("rcp.approx.f32 %0, %1;" : "=f"(r) : "f"(1.0f + e));
  return r;
}
__device__ __forceinline__ uint32_t s2u(const void* p) {
  return (uint32_t)__cvta_generic_to_shared(p);
}
__device__ __forceinline__ void cp16(uint32_t d, const void* s) {
  asm volatile("cp.async.cg.shared.global [%0], [%1], 16;\n" :: "r"(d), "l"(s));
}
__device__ __forceinline__ void cpcommit() { asm volatile("cp.async.commit_group;\n"); }
template <int N> __device__ __forceinline__ void cpwait() {
  asm volatile("cp.async.wait_group %0;\n" :: "n"(N));
}

#define MMA_BF16(acc, a0, a1, a2, a3, b0, b1)                                   \
  asm volatile(                                                                 \
      "mma.sync.aligned.m16n8k16.row.col.f32.bf16.bf16.f32 "                    \
      "{%0,%1,%2,%3}, {%4,%5,%6,%7}, {%8,%9}, {%0,%1,%2,%3};"                   \
      : "+f"(acc[0]), "+f"(acc[1]), "+f"(acc[2]), "+f"(acc[3])                  \
      : "r"(a0), "r"(a1), "r"(a2), "r"(a3), "r"(b0), "r"(b1))

// ---------------- preamble kernels ----------------
__global__ void k_dinv(const float* __restrict__ A) {
  int row = blockIdx.x;
  const float* ap = A + (size_t)row * N_;
  float s = 0.0f;
  for (int m = threadIdx.x; m < N_; m += blockDim.x) s += ap[m];
  __shared__ float red[128];
  red[threadIdx.x] = s;
  __syncthreads();
  for (int off = 64; off; off >>= 1) {
    if (threadIdx.x < off) red[threadIdx.x] += red[threadIdx.x + off];
    __syncthreads();
  }
  if (threadIdx.x == 0) {
    float d = red[0];
    g_dinv[row] = (d > 0.0f) ? (1.0f / sqrtf(d)) : 0.0f;
  }
}

// Normalize An and pack straight into mma B fragments (bf16 hi/lo).
__global__ void k_an(const float* __restrict__ A) {
  #pragma unroll 1
  for (int it = 0; it < 4; it++) {
    int i = blockIdx.x * blockDim.x + threadIdx.x + it * 524288;
    int m = i & 511;
    int r = (i >> 9) & 511;
    int b = i >> 18;
    float v = A[i] * g_dinv[b * N_ + r] * g_dinv[b * N_ + m];
    __nv_bfloat16 hi = __float2bfloat16_rn(v);
    __nv_bfloat16 lo = __float2bfloat16_rn(v - __bfloat162float(hi));
    int tile = r >> 5, n = r & 31;
    int chunk = m >> 7, kp = m & 127;
    int ks = kp >> 4;
    int j = (kp >> 3) & 1, tg = (kp & 7) >> 1, par = m & 1;
    int nt = n >> 3, g = n & 7, lane = g * 4 + tg;
    int u = ((b * 16 + tile) * 4 + chunk) * 4096 + (ks * 4 + nt) * 64 + lane * 2 + j;
    ((__nv_bfloat16*)g_Anb)[u * 2 + par] = hi;
    ((__nv_bfloat16*)g_Anb)[(u + 2048) * 2 + par] = lo;
  }
}

__global__ void k_init(const float* __restrict__ X, const float* __restrict__ Wse,
                       const float* __restrict__ bse, float* __restrict__ out) {
  int tid = blockIdx.x * blockDim.x + threadIdx.x;
  int row = tid >> 7;
  int c = tid & 127;
  const float* x0 = X + (size_t)row * (T_ * NIN_);
  float acc = bse[c];
  #pragma unroll 8
  for (int k = 0; k < NIN_; k++) acc += x0[k] * Wse[k * NEMB_ + c];
  g_es[(size_t)row * NEMB_ + c] = acc;
  g_c[tid] = 0.0f;
  __nv_bfloat16 z = __float2bfloat16_rn(0.0f);
  ((__nv_bfloat16*)g_hb_hi32[0])[tid] = z;
  ((__nv_bfloat16*)g_hb_lo32[0])[tid] = z;
  int b = row >> 9, node = row & 511;
  ((__nv_bfloat16*)g_hbT_hi32[0])[((size_t)(b * 128 + c)) * 512 + node] = z;
  ((__nv_bfloat16*)g_hbT_lo32[0])[((size_t)(b * 128 + c)) * 512 + node] = z;
  if (c < NIN_) out[(size_t)row * (T_ * NIN_) + c] = x0[c];
}

struct StepP {
  const float *Wpe, *bpe, *Wii, *bii, *Whi, *bhi, *Wif, *bif, *Whf, *bhf,
              *Wig, *big, *Whg, *bhg, *Wio, *bio, *Who, *bho, *Wout, *bout;
  float* out;
};

__device__ __forceinline__ float fused_w(const StepP& p, int k, int q, int hcol) {
  const float* Wx = q == 0 ? p.Wii : q == 1 ? p.Wif : q == 2 ? p.Wig : p.Wio;
  if (k < 128) return Wx[k * 128 + hcol];
  if (k < 256) {
    float s = 0.0f;
    #pragma unroll 4
    for (int m = 0; m < 128; m++)
      s += p.Wpe[(k - 128) * 128 + m] * Wx[(128 + m) * 128 + hcol];
    return s;
  }
  const float* Wh = q == 0 ? p.Whi : q == 1 ? p.Whf : q == 2 ? p.Whg : p.Who;
  return Wh[(k - 256) * 128 + hcol];
}

__device__ __forceinline__ u32 pack_bf(float a, float b) {
  __nv_bfloat16 ha = __float2bfloat16_rn(a), hb = __float2bfloat16_rn(b);
  return (u32)__bfloat16_as_ushort(ha) | ((u32)__bfloat16_as_ushort(hb) << 16);
}

// Pack fused gate rows 128:384 (H part with Wpe fold | h part) into 8 chunks;
// also the permuted fused bias (consumed by k_pre_es).
__global__ void k_fuse(StepP p) {
  int idx = blockIdx.x * blockDim.x + threadIdx.x;   // 0..65535
  if (idx < 65536) {
    int np = idx & 511;
    int kp = idx >> 9;                 // 0..127 (pairs in packed k-space 0..255)
    int k0 = kp * 2;
    int hcol = np >> 2, q = np & 3;
    float v0 = fused_w(p, 128 + k0, q, hcol);
    float v1 = fused_w(p, 128 + k0 + 1, q, hcol);
    __nv_bfloat16 h0 = __float2bfloat16_rn(v0), h1 = __float2bfloat16_rn(v1);
    float l0 = v0 - __bfloat162float(h0), l1 = v1 - __bfloat162float(h1);
    int kc = k0 >> 5, kt = (k0 >> 4) & 1, kr = k0 & 15;
    int j = kr >> 3, tg = (kr & 7) >> 1;
    int nt = np >> 3, g = np & 7, lane = g * 4 + tg;
    int w = kc * 16384 + ((kt * 64 + nt) * 32 + lane) * 2 + j;
    g_Wzb[w] = (u32)__bfloat16_as_ushort(h0) | ((u32)__bfloat16_as_ushort(h1) << 16);
    g_Wzb[w + 8192] = pack_bf(l0, l1);
  }
  if (idx < 512) {
    int hcol = idx >> 2, q = idx & 3;
    const float* Wx = q == 0 ? p.Wii : q == 1 ? p.Wif : q == 2 ? p.Wig : p.Wio;
    const float* bx = q == 0 ? p.bii : q == 1 ? p.bif : q == 2 ? p.big : p.bio;
    const float* bh = q == 0 ? p.bhi : q == 1 ? p.bhf : q == 2 ? p.bhg : p.bho;
    float s = bx[hcol] + bh[hcol];
    #pragma unroll 4
    for (int m = 0; m < 128; m++)
      s += p.bpe[m] * Wx[(128 + m) * 128 + hcol];
    g_bzp[idx] = s;
  }
}

// pre_es = es @ Wz[0:128] + bzp, stored in accumulator-fragment layout.
__global__ void k_pre_es(StepP p) {
  int idx = blockIdx.x * blockDim.x + threadIdx.x;   // 524288
  int lane = idx & 31, n = (idx >> 5) & 15, wrp = (idx >> 9) & 7;
  int tile = (idx >> 12) & 15, b = idx >> 16;
  int g = lane >> 2, tg = lane & 3;
  int row = b * 512 + tile * 32 + (wrp & 1) * 16 + g;
  int c0 = ((wrp >> 1) * 16 + n) * 8 + 2 * tg;
  int c1 = c0 + 1;
  int hcol0 = c0 >> 2, q0 = c0 & 3;
  int hcol1 = c1 >> 2, q1 = c1 & 3;
  const float* W0 = (q0 == 0 ? p.Wii : q0 == 1 ? p.Wif : q0 == 2 ? p.Wig : p.Wio);
  const float* W1 = (q1 == 0 ? p.Wii : q1 == 1 ? p.Wif : q1 == 2 ? p.Wig : p.Wio);
  const float* e0 = g_es + (size_t)row * 128;
  const float* e8 = g_es + (size_t)(row + 8) * 128;
  float a0 = g_bzp[c0], a1 = g_bzp[c1];
  float a2 = a0, a3 = a1;
  #pragma unroll 4
  for (int k = 0; k < 128; k++) {
    float w0 = W0[k * 128 + hcol0], w1 = W1[k * 128 + hcol1];
    float x0 = e0[k], x8 = e8[k];
    a0 += x0 * w0; a1 += x0 * w1;
    a2 += x8 * w0; a3 += x8 * w1;
  }
  g_preES[idx] = make_float4(a0, a1, a2, a3);
}

// ---------------- step kernel ----------------
// smem: zbh [32][264] bf16 = 16896 ; zbl same ; BUF = 172032 (GEMM1 2x86016 /
// gates Wch 2x65536 + WoutS 32768)
#define SMB_ZBH  0
#define SMB_ZBL  16896
#define SMB_BUF  33792
#define SM_BYTES 205824

// Stage one GEMM1 chunk (h^T hi/lo slice + An fragment block) into buffer nb.
__device__ __forceinline__ void stage_g1(
    char* smc, int tid, int b, const char* hbT_h, const char* hbT_l,
    const char* anb, int chunk, int nb) {
  char* base = smc + SMB_BUF + nb * 86016;
  int k0 = chunk * 128;
  #pragma unroll
  for (int j = 0; j < 8; j++) {
    int idx = tid + j * 256;
    int row = idx >> 4, c16 = idx & 15;
    long so = (long)(b * 128 + row) * 1024 + (k0 + c16 * 8) * 2;
    cp16(s2u(base + row * 272 + c16 * 16), hbT_h + so);
    cp16(s2u(base + 34816 + row * 272 + c16 * 16), hbT_l + so);
  }
  #pragma unroll
  for (int j = 0; j < 4; j++) {
    int idx = tid + j * 256;
    cp16(s2u(base + 69632 + idx * 16), anb + (size_t)chunk * 16384 + idx * 16);
  }
}

__global__ void __launch_bounds__(256, 1) k_step(StepP p, int t) {
  extern __shared__ char smc[];
  __nv_bfloat16* zbh = (__nv_bfloat16*)(smc + SMB_ZBH);   // [32][264]: 0:128 H | 128:256 h_prev
  __nv_bfloat16* zbl = (__nv_bfloat16*)(smc + SMB_ZBL);
  float* hS = (float*)(smc + SMB_ZBH);                    // [32][132] after gate phase
  u32*   Wch = (u32*)(smc + SMB_BUF);
  float* WoutS = (float*)(smc + SMB_BUF + 131072);

  const int ph = (t - 1) & 1, pn = t & 1;
  const int b = blockIdx.y;
  const int r0 = blockIdx.x * 32;
  const int tid = threadIdx.x;
  const int wrp = tid >> 5, lane = tid & 31;
  const int g = lane >> 2, tg = lane & 3;
  const int baserow = b * N_ + r0;

  // --- stage zb: h_prev into cols 128:256 (hi/lo) ---
  {
    const char* hh = (const char*)g_hb_hi32[ph];
    const char* hl = (const char*)g_hb_lo32[ph];
    #pragma unroll
    for (int j = 0; j < 4; j++) {
      int idx = tid + (j & 1) * 256;
      int r = idx >> 4, c16 = idx & 15;
      long so = (long)(baserow + r) * 256 + c16 * 16;
      if (j < 2) cp16(s2u((char*)zbh + r * 528 + 256 + c16 * 16), hh + so);
      else       cp16(s2u((char*)zbl + r * 528 + 256 + c16 * 16), hl + so);
    }
  }
  cpcommit();

  // --- GEMM1 (mma): D^T[128 hcol x 32 node] = h^T @ An^T, K=512, 4 chunks ---
  const char* hbT_h = (const char*)g_hbT_hi32[ph];
  const char* hbT_l = (const char*)g_hbT_lo32[ph];
  const char* anb = (const char*)(g_Anb + ((b * 16 + (r0 >> 5)) * 4) * 4096);

  stage_g1(smc, tid, b, hbT_h, hbT_l, anb, 0, 0);
  cpcommit();

  float aG[4][4];
  #pragma unroll
  for (int n = 0; n < 4; n++)
    #pragma unroll
    for (int j = 0; j < 4; j++) aG[n][j] = 0.0f;

  const int arow = wrp * 16 + g;

  #pragma unroll 1
  for (int ch = 0; ch < 4; ch++) {
    if (ch < 3) {
      stage_g1(smc, tid, b, hbT_h, hbT_l, anb, ch + 1, (ch + 1) & 1);
      cpcommit();
      cpwait<1>();
    } else {
      cpwait<0>();
    }
    __syncthreads();
    const char* base = smc + SMB_BUF + (ch & 1) * 86016;
    const __nv_bfloat16* Ah = (const __nv_bfloat16*)base;
    const __nv_bfloat16* Al = (const __nv_bfloat16*)(base + 34816);
    const u32* Bf = (const u32*)(base + 69632);
    #pragma unroll 2
    for (int ks = 0; ks < 8; ks++) {
      int kk = ks * 16 + tg * 2;
      u32 ah0 = *(const u32*)(Ah + arow * 136 + kk);
      u32 ah1 = *(const u32*)(Ah + (arow + 8) * 136 + kk);
      u32 ah2 = *(const u32*)(Ah + arow * 136 + kk + 8);
      u32 ah3 = *(const u32*)(Ah + (arow + 8) * 136 + kk + 8);
      u32 al0 = *(const u32*)(Al + arow * 136 + kk);
      u32 al1 = *(const u32*)(Al + (arow + 8) * 136 + kk);
      u32 al2 = *(const u32*)(Al + arow * 136 + kk + 8);
      u32 al3 = *(const u32*)(Al + (arow + 8) * 136 + kk + 8);
      #pragma unroll
      for (int nt = 0; nt < 4; nt++) {
        const u32* bp = Bf + (ks * 4 + nt) * 64 + lane * 2;
        uint2 bh = *(const uint2*)bp;
        uint2 bl = *(const uint2*)(bp + 2048);
        MMA_BF16(aG[nt], ah0, ah1, ah2, ah3, bh.x, bh.y);
        MMA_BF16(aG[nt], ah0, ah1, ah2, ah3, bl.x, bl.y);
        MMA_BF16(aG[nt], al0, al1, al2, al3, bh.x, bh.y);
      }
    }
    __syncthreads();
  }

  // write H (split hi/lo) into zb cols 0:128
  #pragma unroll
  for (int nt = 0; nt < 4; nt++) {
    #pragma unroll
    for (int j = 0; j < 4; j++) {
      float v = aG[nt][j];
      int hcol = wrp * 16 + g + 8 * (j >> 1);
      int nrow = nt * 8 + tg * 2 + (j & 1);
      __nv_bfloat16 hi = __float2bfloat16_rn(v);
      __nv_bfloat16 lo = __float2bfloat16_rn(v - __bfloat162float(hi));
      zbh[nrow * 264 + hcol] = hi;
      zbl[nrow * 264 + hcol] = lo;
    }
  }

  // prefetch gate chunk 0 + Wout (GEMM1 buffers are dead)
  #pragma unroll
  for (int j = 0; j < 16; j++) {
    int idx = tid + j * 256;
    cp16(s2u((char*)Wch + idx * 16), (const char*)g_Wzb + idx * 16);
  }
  #pragma unroll
  for (int j = 0; j < 8; j++) {
    int idx = tid + j * 256;
    int r = idx >> 4, c4 = (idx & 15) * 4;
    cp16(s2u(WoutS + r * 64 + c4), p.Wout + r * 64 + c4);
  }
  cpcommit();

  // --- gate GEMM: pre[32x512'] = z[32x256] @ Wz + pre_es, 8 chunks of 32 k ---
  const int mt = wrp & 1;
  const int nr = wrp >> 1;

  float acc[16][4];
  {
    const float4* pe =
        g_preES + ((size_t)((b * 16 + (r0 >> 5)) * 8 + wrp) * 16) * 32 + lane;
    #pragma unroll
    for (int n = 0; n < 16; n++) {
      float4 v = pe[n * 32];
      acc[n][0] = v.x; acc[n][1] = v.y; acc[n][2] = v.z; acc[n][3] = v.w;
    }
  }

  #pragma unroll 1
  for (int ch = 0; ch < 8; ch++) {
    if (ch < 7) {
      int nb = (ch + 1) & 1;
      const char* src = (const char*)g_Wzb + (size_t)(ch + 1) * 65536;
      #pragma unroll
      for (int j = 0; j < 16; j++) {
        int idx = tid + j * 256;
        cp16(s2u((char*)Wch + nb * 65536 + idx * 16), src + idx * 16);
      }
      cpcommit();
      cpwait<1>();
    } else {
      cpwait<0>();
    }
    __syncthreads();
    const u32* Wc = Wch + (ch & 1) * 16384;
    #pragma unroll
    for (int kt = 0; kt < 2; kt++) {
      int kb = ch * 32 + kt * 16 + 2 * tg;
      int ra = mt * 16 + g;
      u32 ah0 = *(const u32*)(zbh + ra * 264 + kb);
      u32 ah1 = *(const u32*)(zbh + (ra + 8) * 264 + kb);
      u32 ah2 = *(const u32*)(zbh + ra * 264 + kb + 8);
      u32 ah3 = *(const u32*)(zbh + (ra + 8) * 264 + kb + 8);
      u32 al0 = *(const u32*)(zbl + ra * 264 + kb);
      u32 al1 = *(const u32*)(zbl + (ra + 8) * 264 + kb);
      u32 al2 = *(const u32*)(zbl + ra * 264 + kb + 8);
      u32 al3 = *(const u32*)(zbl + (ra + 8) * 264 + kb + 8);
      const u32* base = Wc + (kt * 64 + nr * 16) * 64 + lane * 2;
      #pragma unroll
      for (int n = 0; n < 16; n++) {
        uint2 bh = *(const uint2*)(base + n * 64);
        uint2 bl = *(const uint2*)(base + 8192 + n * 64);
        MMA_BF16(acc[n], ah0, ah1, ah2, ah3, bh.x, bh.y);
        MMA_BF16(acc[n], ah0, ah1, ah2, ah3, bl.x, bl.y);
        MMA_BF16(acc[n], al0, al1, al2, al3, bh.x, bh.y);
      }
    }
    __syncthreads();
  }

  // --- pointwise LSTM; h_t -> hS (aliases zbh region, safe after final sync) ---
  {
    int odd = tg & 1;
    #pragma unroll
    for (int n = 0; n < 16; n++) {
      float c0 = acc[n][0], c1 = acc[n][1], c2 = acc[n][2], c3 = acc[n][3];
      float sa = odd ? c0 : c2;
      float sb = odd ? c1 : c3;
      float ra = __shfl_xor_sync(0xffffffffu, sa, 1);
      float rb = __shfl_xor_sync(0xffffffffu, sb, 1);
      float pi = odd ? ra : c0;
      float pf = odd ? rb : c1;
      float pg = odd ? c2 : ra;
      float po = odd ? c3 : rb;
      int row = mt * 16 + g + 8 * odd;
      int hcol = nr * 32 + n * 2 + (tg >> 1);
      int gr = baserow + row;
      float cold = g_c[(size_t)gr * NH_ + hcol];
      float iv = fsgm(pi), fv = fsgm(pf);
      float gv = tanhf(pg), ov = fsgm(po);
      float cn = fv * cold + iv * gv;
      float hv = ov * tanhf(cn);
      g_c[(size_t)gr * NH_ + hcol] = cn;
      hS[row * 132 + hcol] = hv;
    }
  }
  __syncthreads();

  // --- write h_t to global in bf16 hi/lo, row-major + transposed ---
  {
    u32* hbh = (u32*)g_hb_hi32[pn];
    u32* hbl = (u32*)g_hb_lo32[pn];
    #pragma unroll
    for (int j = 0; j < 8; j++) {
      int idx = tid + j * 256;
      int row = idx >> 6, cp_ = idx & 63;
      float f0 = hS[row * 132 + cp_ * 2];
      float f1 = hS[row * 132 + cp_ * 2 + 1];
      __nv_bfloat16 h0 = __float2bfloat16_rn(f0), h1 = __float2bfloat16_rn(f1);
      hbh[(size_t)(baserow + row) * 64 + cp_] =
          (u32)__bfloat16_as_ushort(h0) | ((u32)__bfloat16_as_ushort(h1) << 16);
      hbl[(size_t)(baserow + row) * 64 + cp_] =
          pack_bf(f0 - __bfloat162float(h0), f1 - __bfloat162float(h1));
    }
    u32* hTh = (u32*)g_hbT_hi32[pn];
    u32* hTl = (u32*)g_hbT_lo32[pn];
    #pragma unroll
    for (int j = 0; j < 8; j++) {
      int idx = tid + j * 256;
      int hcol = idx >> 4, jp = idx & 15;
      float f0 = hS[(2 * jp) * 132 + hcol];
      float f1 = hS[(2 * jp + 1) * 132 + hcol];
      __nv_bfloat16 h0 = __float2bfloat16_rn(f0), h1 = __float2bfloat16_rn(f1);
      size_t o = (size_t)(b * 128 + hcol) * 256 + (r0 >> 1) + jp;
      hTh[o] = (u32)__bfloat16_as_ushort(h0) | ((u32)__bfloat16_as_ushort(h1) << 16);
      hTl[o] = pack_bf(f0 - __bfloat162float(h0), f1 - __bfloat162float(h1));
    }
  }

  // --- out[t] = out[t-1] + h @ Wout + bout (fp32 FFMA2, small) ---
  {
    const int rA = tid >> 4, rB = rA + 16;
    const int co0 = (tid & 15) * 4;
    const ulonglong2* bp = (const ulonglong2*)(p.bout + co0);
    ulonglong2 bb = bp[0];
    u64 oa00 = bb.x, oa01 = bb.y, oa10 = bb.x, oa11 = bb.y;
    #pragma unroll 4
    for (int k = 0; k < NH_; k += 4) {
      float4 a0v = *(const float4*)(hS + rA * 132 + k);
      float4 a1v = *(const float4*)(hS + rB * 132 + k);
      float a0c[4] = {a0v.x, a0v.y, a0v.z, a0v.w};
      float a1c[4] = {a1v.x, a1v.y, a1v.z, a1v.w};
      #pragma unroll
      for (int s = 0; s < 4; s++) {
        u64 A0 = bc2(a0c[s]), A1 = bc2(a1c[s]);
        ulonglong2 w = *(const ulonglong2*)(WoutS + (k + s) * 64 + co0);
        fma2(oa00, A0, w.x); fma2(oa01, A0, w.y);
        fma2(oa10, A1, w.x); fma2(oa11, A1, w.y);
      }
    }
    #pragma unroll
    for (int rr = 0; rr < 2; rr++) {
      int r = (rr ? rB : rA);
      size_t gb = (size_t)(baserow + r) * (T_ * NIN_);
      float4 prev = *(const float4*)(p.out + gb + (size_t)(t - 1) * NIN_ + co0);
      float x0, x1, x2, x3;
      if (rr == 0) { up2(oa00, x0, x1); up2(oa01, x2, x3); }
      else         { up2(oa10, x0, x1); up2(oa11, x2, x3); }
      float4 nw = make_float4(prev.x + x0, prev.y + x1, prev.z + x2, prev.w + x3);
      *(float4*)(p.out + gb + (size_t)t * NIN_ + co0) = nw;
    }
  }
}

// ---------------- host launch ----------------
extern "C" void kernel_launch(void* const* d_in, const int* in_sizes, int n_in,
                              void* d_out, int out_size) {
  const float* X   = (const float*)d_in[0];
  const float* A   = (const float*)d_in[1];
  const float* Wse = (const float*)d_in[2];
  const float* bse = (const float*)d_in[3];
  StepP p;
  p.Wpe  = (const float*)d_in[4];  p.bpe  = (const float*)d_in[5];
  p.Wii  = (const float*)d_in[6];  p.bii  = (const float*)d_in[7];
  p.Whi  = (const float*)d_in[8];  p.bhi  = (const float*)d_in[9];
  p.Wif  = (const float*)d_in[10]; p.bif  = (const float*)d_in[11];
  p.Whf  = (const float*)d_in[12]; p.bhf  = (const float*)d_in[13];
  p.Wig  = (const float*)d_in[14]; p.big  = (const float*)d_in[15];
  p.Whg  = (const float*)d_in[16]; p.bhg  = (const float*)d_in[17];
  p.Wio  = (const float*)d_in[18]; p.bio  = (const float*)d_in[19];
  p.Who  = (const float*)d_in[20]; p.bho  = (const float*)d_in[21];
  p.Wout = (const float*)d_in[22]; p.bout = (const float*)d_in[23];
  p.out  = (float*)d_out;

  cudaFuncSetAttribute(k_step, cudaFuncAttributeMaxDynamicSharedMemorySize, SM_BYTES);

  k_dinv<<<ROWS_, 128>>>(A);
  k_an<<<2048, 256>>>(A);
  k_fuse<<<256, 256>>>(p);
  k_init<<<2048, 256>>>(X, Wse, bse, p.out);
  k_pre_es<<<2048, 256>>>(p);
  for (int t = 1; t < T_; t++) {
    k_step<<<dim3(N_ / 32, B_), 256, SM_BYTES>>>(p, t);
  }
}